// round 14
// baseline (speedup 1.0000x reference)
#include <cuda_runtime.h>
#include <cuda_bf16.h>
#include <cstdint>
#include <math.h>

#define BB 16
#define NN 32768
#define DD 256
#define EE 512
#define HH 8
#define KK 512
#define TT 16
#define NC 4      // attention key chunks
#define CK 128    // keys per chunk

typedef __nv_bfloat16 bf16;

// ---------------- device scratch (no allocations allowed) ----------------
__device__ float g_x[BB * KK * EE];          // projected x fp32
__device__ bf16  g_xh[BB * KK * EE];         // x hi/lo (bf16) for kv gemm
__device__ bf16  g_xl[BB * KK * EE];
__device__ bf16  g_wph[EE * DD];             // proj_w hi/lo
__device__ bf16  g_wpl[EE * DD];
__device__ bf16  g_wkh[2 * EE * EE];         // kv weight hi/lo
__device__ bf16  g_wkl[2 * EE * EE];
__device__ float g_kv[BB * KK * 2 * EE];     // k|v concat fp32
__device__ float g_q[BB * TT * EE];          // scaled q
__device__ float g_o[BB * TT * EE];          // attn out
__device__ float g_z[BB * TT * EE];          // post layernorm
__device__ float g_part[4 * BB * TT * EE];   // split-K / attn partials
__device__ float g_m[NC * BB * HH * TT];
__device__ float g_l[NC * BB * HH * TT];
__device__ int   g_idx[BB * KK];

// order-preserving float->uint key (bigger key == bigger float)
__device__ __forceinline__ unsigned fkey(float f) {
    unsigned u = __float_as_uint(f);
    return (u & 0x80000000u) ? ~u : (u | 0x80000000u);
}

__device__ __forceinline__ void split_bf16(float f, bf16& h, bf16& l) {
    h = __float2bfloat16(f);
    l = __float2bfloat16(f - __bfloat162float(h));
}

__device__ __forceinline__ uint32_t pk2(bf16 a, bf16 b) {
    return (uint32_t)__bfloat16_as_ushort(a) |
           ((uint32_t)__bfloat16_as_ushort(b) << 16);
}

// split 8 floats (two float4) into packed hi uint4 / lo uint4
__device__ __forceinline__ void pack8(float4 a, float4 b, uint4& h, uint4& l) {
    bf16 h0, l0, h1, l1;
    split_bf16(a.x, h0, l0); split_bf16(a.y, h1, l1);
    h.x = pk2(h0, h1); l.x = pk2(l0, l1);
    split_bf16(a.z, h0, l0); split_bf16(a.w, h1, l1);
    h.y = pk2(h0, h1); l.y = pk2(l0, l1);
    split_bf16(b.x, h0, l0); split_bf16(b.y, h1, l1);
    h.z = pk2(h0, h1); l.z = pk2(l0, l1);
    split_bf16(b.z, h0, l0); split_bf16(b.w, h1, l1);
    h.w = pk2(h0, h1); l.w = pk2(l0, l1);
}

__device__ __forceinline__ void cp16(uint32_t s, const void* g) {
    asm volatile("cp.async.cg.shared.global [%0], [%1], 16;" :: "r"(s), "l"(g));
}

// ---------------- top-K: smem-resident keys, radix select + bitonic sort ----
extern __shared__ unsigned skeys[];   // NN unsigned = 128 KB dynamic smem

__global__ void __launch_bounds__(1024) topk_kernel(const float* __restrict__ scores) {
    const int b = blockIdx.x;
    const float* s = scores + (size_t)b * NN;
    const int tid = threadIdx.x;

    __shared__ unsigned hist[256];
    __shared__ unsigned sh_prefix, sh_mask, sh_remk;
    __shared__ int sh_cntgt, sh_cnteq;
    __shared__ unsigned long long sel[512];
    __shared__ int eq[1024];

    if (tid == 0) { sh_prefix = 0u; sh_mask = 0u; sh_remk = KK; }
    if (tid < 256) hist[tid] = 0u;
    __syncthreads();

    for (int i = tid; i < NN; i += 1024) {
        unsigned k = fkey(__ldg(&s[i]));
        skeys[i] = k;
        atomicAdd(&hist[k >> 24], 1u);
    }
    __syncthreads();

    for (int pass = 0; pass < 4; pass++) {
        const int shift = 24 - pass * 8;
        if (tid == 0) {
            unsigned remk = sh_remk, acc = 0u;
            int d;
            for (d = 255; d >= 0; d--) {
                if (acc + hist[d] >= remk) break;
                acc += hist[d];
            }
            sh_remk  = remk - acc;
            sh_prefix = sh_prefix | ((unsigned)d << shift);
            sh_mask   = sh_mask | (0xFFu << shift);
            sh_cntgt = 0; sh_cnteq = 0;
        }
        __syncthreads();
        if (pass == 3) break;
        if (tid < 256) hist[tid] = 0u;
        __syncthreads();
        const unsigned prefix = sh_prefix, mask = sh_mask;
        const int nshift = shift - 8;
        for (int i = tid; i < NN; i += 1024) {
            unsigned k = skeys[i];
            if ((k & mask) == prefix) atomicAdd(&hist[(k >> nshift) & 255u], 1u);
        }
        __syncthreads();
    }

    const unsigned Tkey = sh_prefix;
    const int remk = (int)sh_remk;

    for (int i = tid; i < NN; i += 1024) {
        unsigned k = skeys[i];
        if (k > Tkey) {
            int p = atomicAdd(&sh_cntgt, 1);
            sel[p] = ((unsigned long long)k << 32) | (unsigned)(0xFFFFFFFFu - (unsigned)i);
        } else if (k == Tkey) {
            int p = atomicAdd(&sh_cnteq, 1);
            if (p < 1024) eq[p] = i;
        }
    }
    __syncthreads();
    const int cntgt = sh_cntgt;
    const int cnteq = min(sh_cnteq, 1024);

    if (tid >= cnteq) eq[tid] = 0x7FFFFFFF;
    __syncthreads();
    for (unsigned k = 2; k <= 1024; k <<= 1)
        for (unsigned j = k >> 1; j > 0; j >>= 1) {
            unsigned i = tid, ixj = i ^ j;
            if (ixj > i) {
                int a = eq[i], c = eq[ixj];
                bool up = ((i & k) == 0);
                if ((a > c) == up) { eq[i] = c; eq[ixj] = a; }
            }
            __syncthreads();
        }
    for (int jj = tid; jj < remk; jj += 1024)
        sel[cntgt + jj] = ((unsigned long long)Tkey << 32) |
                          (unsigned)(0xFFFFFFFFu - (unsigned)eq[jj]);
    __syncthreads();

    for (unsigned k = 2; k <= 512; k <<= 1)
        for (unsigned j = k >> 1; j > 0; j >>= 1) {
            if (tid < 512) {
                unsigned i = tid, ixj = i ^ j;
                if (ixj > i) {
                    unsigned long long a = sel[i], c = sel[ixj];
                    bool up = ((i & k) == 0);
                    if ((a > c) == up) { sel[i] = c; sel[ixj] = a; }
                }
            }
            __syncthreads();
        }
    if (tid < 512)
        g_idx[b * KK + tid] =
            (int)(0xFFFFFFFFu - (unsigned)(sel[511 - tid] & 0xFFFFFFFFull));
}

// -------- weight split: proj_w and kv weights in ONE launch ---------------
__global__ void __launch_bounds__(128)
conv_w_all(const float* __restrict__ Wp, const float* __restrict__ Wkv) {
    const int r = blockIdx.x;   // 0..EE+2EE-1
    if (r < EE) {
        for (int c = threadIdx.x; c < DD; c += 128) {
            bf16 h, l;
            split_bf16(Wp[(size_t)r * DD + c], h, l);
            g_wph[(size_t)r * DD + c] = h;
            g_wpl[(size_t)r * DD + c] = l;
        }
    } else {
        const int rr = r - EE;
        for (int c = threadIdx.x; c < EE; c += 128) {
            bf16 h, l;
            split_bf16(Wkv[(size_t)rr * EE + c], h, l);
            g_wkh[(size_t)rr * EE + c] = h;
            g_wkl[(size_t)rr * EE + c] = l;
        }
    }
}

// ============== tensor-core split-bf16 GEMM infrastructure =================
// CTA tile 128x128, warp tile 32x64, mma m16n8k16 x 3 products (hh, hl, lh).
#define AP 40          // smem pitch in bf16 (80B: conflict-free ldmatrix)
#define SA_ELEM (128 * AP)
#define SW_ELEM (128 * AP)
#define TC_SMEM ((2 * SA_ELEM + 2 * SW_ELEM) * 2 * 2)  // 81920 bytes

__device__ __forceinline__ void ldsm4(uint32_t r[4], uint32_t addr) {
    asm volatile("ldmatrix.sync.aligned.m8n8.x4.shared.b16 {%0,%1,%2,%3}, [%4];"
                 : "=r"(r[0]), "=r"(r[1]), "=r"(r[2]), "=r"(r[3]) : "r"(addr));
}
__device__ __forceinline__ void mma_bf16(float c[4], const uint32_t a[4],
                                         uint32_t b0, uint32_t b1) {
    asm volatile(
        "mma.sync.aligned.m16n8k16.row.col.f32.bf16.bf16.f32 "
        "{%0,%1,%2,%3}, {%4,%5,%6,%7}, {%8,%9}, {%0,%1,%2,%3};"
        : "+f"(c[0]), "+f"(c[1]), "+f"(c[2]), "+f"(c[3])
        : "r"(a[0]), "r"(a[1]), "r"(a[2]), "r"(a[3]), "r"(b0), "r"(b1));
}

#define LOAD_A_F32(K0)                                                    \
    {                                                                     \
        float4 x0 = *(const float4*)(gA0 + (K0));                         \
        float4 x1 = *(const float4*)(gA0 + (K0) + 4);                     \
        float4 y0 = *(const float4*)(gA1 + (K0));                         \
        float4 y1 = *(const float4*)(gA1 + (K0) + 4);                     \
        pack8(x0, x1, pAh0, pAl0);                                        \
        pack8(y0, y1, pAh1, pAl1);                                        \
    }

#define LOAD_W_ASYNC(BUF, K0)                                             \
    {                                                                     \
        cp16(baseWh + 2u * ((BUF) * SW_ELEM + arow * AP + achk), gWh0 + (K0)); \
        cp16(baseWh + 2u * ((BUF) * SW_ELEM + (arow + 64) * AP + achk), gWh1 + (K0)); \
        cp16(baseWl + 2u * ((BUF) * SW_ELEM + arow * AP + achk), gWl0 + (K0)); \
        cp16(baseWl + 2u * ((BUF) * SW_ELEM + (arow + 64) * AP + achk), gWl1 + (K0)); \
    }

#define LOAD_A_ASYNC(BUF, K0)                                             \
    {                                                                     \
        cp16(baseAh + 2u * ((BUF) * SA_ELEM + arow * AP + achk), gAh0 + (K0)); \
        cp16(baseAh + 2u * ((BUF) * SA_ELEM + (arow + 64) * AP + achk), gAh1 + (K0)); \
        cp16(baseAl + 2u * ((BUF) * SA_ELEM + arow * AP + achk), gAl0 + (K0)); \
        cp16(baseAl + 2u * ((BUF) * SA_ELEM + (arow + 64) * AP + achk), gAl1 + (K0)); \
    }

#define CP_COMMIT() asm volatile("cp.async.commit_group;\n" ::: "memory")
#define CP_WAIT0()  asm volatile("cp.async.wait_group 0;\n" ::: "memory")

#define STS_A(BUF)                                                        \
    {                                                                     \
        *(uint4*)&sAh[(BUF) * SA_ELEM + arow * AP + achk]        = pAh0;  \
        *(uint4*)&sAh[(BUF) * SA_ELEM + (arow + 64) * AP + achk] = pAh1;  \
        *(uint4*)&sAl[(BUF) * SA_ELEM + arow * AP + achk]        = pAl0;  \
        *(uint4*)&sAl[(BUF) * SA_ELEM + (arow + 64) * AP + achk] = pAl1;  \
    }

#define TC_COMPUTE(BUF)                                                   \
    _Pragma("unroll")                                                     \
    for (int ks = 0; ks < 32; ks += 16) {                                 \
        uint32_t ah[2][4], al[2][4];                                      \
        _Pragma("unroll")                                                 \
        for (int mt = 0; mt < 2; mt++) {                                  \
            uint32_t off = 2u * ((BUF) * SA_ELEM + (wm + mt * 16) * AP + aoffA + ks); \
            ldsm4(ah[mt], baseAh + off);                                  \
            ldsm4(al[mt], baseAl + off);                                  \
        }                                                                 \
        _Pragma("unroll")                                                 \
        for (int hf = 0; hf < 2; hf++) {                                  \
            uint32_t wh[2][4], wl[2][4];                                  \
            _Pragma("unroll")                                             \
            for (int np = 0; np < 2; np++) {                              \
                uint32_t off = 2u * ((BUF) * SW_ELEM + (wn + (hf * 2 + np) * 16) * AP + woffW + ks); \
                ldsm4(wh[np], baseWh + off);                              \
                ldsm4(wl[np], baseWl + off);                              \
            }                                                             \
            _Pragma("unroll")                                             \
            for (int mt = 0; mt < 2; mt++)                                \
                _Pragma("unroll")                                         \
                for (int nt = 0; nt < 4; nt++) {                          \
                    uint32_t bh0 = wh[nt >> 1][(nt & 1) * 2];             \
                    uint32_t bh1 = wh[nt >> 1][(nt & 1) * 2 + 1];         \
                    uint32_t bl0 = wl[nt >> 1][(nt & 1) * 2];             \
                    uint32_t bl1 = wl[nt >> 1][(nt & 1) * 2 + 1];         \
                    mma_bf16(acc[mt][hf * 4 + nt], ah[mt], bh0, bh1);     \
                    mma_bf16(acc[mt][hf * 4 + nt], ah[mt], bl0, bl1);     \
                    mma_bf16(acc[mt][hf * 4 + nt], al[mt], bh0, bh1);     \
                }                                                         \
        }                                                                 \
    }

#define TC_PREAMBLE                                                       \
    extern __shared__ __align__(16) char smraw[];                         \
    bf16* sAh = (bf16*)smraw;                                             \
    bf16* sAl = sAh + 2 * SA_ELEM;                                        \
    bf16* sWh = sAl + 2 * SA_ELEM;                                        \
    bf16* sWl = sWh + 2 * SW_ELEM;                                        \
    const int b = blockIdx.z;                                             \
    const int row0 = blockIdx.y * 128, col0 = blockIdx.x * 128;           \
    const int N = gridDim.x * 128;                                        \
    const int tid = threadIdx.x;                                          \
    const int lane = tid & 31, wid = tid >> 5;                            \
    const int wm = (wid & 3) * 32, wn = (wid >> 2) * 64;                  \
    const uint32_t baseAh = (uint32_t)__cvta_generic_to_shared(sAh);      \
    const uint32_t baseAl = (uint32_t)__cvta_generic_to_shared(sAl);      \
    const uint32_t baseWh = (uint32_t)__cvta_generic_to_shared(sWh);      \
    const uint32_t baseWl = (uint32_t)__cvta_generic_to_shared(sWl);      \
    const uint32_t aoffA = (lane & 15) * AP + ((lane >> 4) << 3);         \
    const uint32_t woffW = ((lane & 7) + ((lane & 16) >> 1)) * AP + (lane & 8); \
    const int arow = tid >> 2;                                            \
    const int achk = (tid & 3) * 8;

#define TC_EPILOGUE                                                       \
    const int g = lane >> 2, tq = (lane & 3) * 2;                         \
    _Pragma("unroll")                                                     \
    for (int mt = 0; mt < 2; mt++)                                        \
        _Pragma("unroll")                                                 \
        for (int nt = 0; nt < 8; nt++) {                                  \
            int r = row0 + wm + mt * 16 + g;                              \
            int cc = col0 + wn + nt * 8 + tq;                             \
            float b0 = bias[cc], b1 = bias[cc + 1];                       \
            float v00 = acc[mt][nt][0] + b0, v01 = acc[mt][nt][1] + b1;   \
            float v10 = acc[mt][nt][2] + b0, v11 = acc[mt][nt][3] + b1;   \
            size_t i0 = (size_t)((long long)b * strideC) + (size_t)r * N + cc; \
            size_t i1 = (size_t)((long long)b * strideC) + (size_t)(r + 8) * N + cc; \
            *(float2*)(C + i0) = make_float2(v00, v01);                   \
            *(float2*)(C + i1) = make_float2(v10, v11);                   \
            if (Ch) {                                                     \
                bf16 h, l;                                                \
                split_bf16(v00, h, l); Ch[i0] = h; Cl[i0] = l;            \
                split_bf16(v01, h, l); Ch[i0 + 1] = h; Cl[i0 + 1] = l;    \
                split_bf16(v10, h, l); Ch[i1] = h; Cl[i1] = l;            \
                split_bf16(v11, h, l); Ch[i1 + 1] = h; Cl[i1 + 1] = l;    \
            }                                                             \
        }

// --- variant A: A fp32 (optionally gathered), split in loader ---------------
__global__ void __launch_bounds__(256, 2)
gemm_tc_f32a(const bf16* __restrict__ Wh, const bf16* __restrict__ Wl,
             const float* __restrict__ bias,
             float* __restrict__ C, long long strideC,
             int Kd,
             const int* __restrict__ idxp, const float* __restrict__ gfeat,
             bf16* __restrict__ Ch, bf16* __restrict__ Cl) {
    TC_PREAMBLE
    const int* ib = idxp + b * KK;
    const float* gA0 = gfeat + ((size_t)b * NN + ib[row0 + arow]) * Kd + achk;
    const float* gA1 = gfeat + ((size_t)b * NN + ib[row0 + arow + 64]) * Kd + achk;
    const bf16* gWh0 = Wh + (size_t)(col0 + arow) * Kd + achk;
    const bf16* gWh1 = Wh + (size_t)(col0 + arow + 64) * Kd + achk;
    const bf16* gWl0 = Wl + (size_t)(col0 + arow) * Kd + achk;
    const bf16* gWl1 = Wl + (size_t)(col0 + arow + 64) * Kd + achk;

    float acc[2][8][4];
#pragma unroll
    for (int mt = 0; mt < 2; mt++)
#pragma unroll
        for (int nt = 0; nt < 8; nt++)
#pragma unroll
            for (int i = 0; i < 4; i++) acc[mt][nt][i] = 0.f;

    uint4 pAh0, pAh1, pAl0, pAl1;
    LOAD_A_F32(0)
    LOAD_W_ASYNC(0, 0)
    CP_COMMIT();
    STS_A(0)
    CP_WAIT0();
    __syncthreads();

    int buf = 0;
    for (int k0 = 32; k0 < Kd; k0 += 32) {
        LOAD_A_F32(k0)
        LOAD_W_ASYNC(buf ^ 1, k0)
        CP_COMMIT();
        TC_COMPUTE(buf)
        STS_A(buf ^ 1)
        CP_WAIT0();
        __syncthreads();
        buf ^= 1;
    }
    TC_COMPUTE(buf)
    TC_EPILOGUE
}

// --- variant B: A pre-split bf16, all operands via cp.async -----------------
__global__ void __launch_bounds__(256, 2)
gemm_tc_bf16a(const bf16* __restrict__ Ah, const bf16* __restrict__ Al,
              long long strideA,
              const bf16* __restrict__ Wh, const bf16* __restrict__ Wl,
              const float* __restrict__ bias,
              float* __restrict__ C, long long strideC,
              int Kd) {
    bf16* Ch = nullptr;
    bf16* Cl = nullptr;
    TC_PREAMBLE
    const long long Aoff = (long long)b * strideA;
    const bf16* gAh0 = Ah + Aoff + (size_t)(row0 + arow) * Kd + achk;
    const bf16* gAh1 = Ah + Aoff + (size_t)(row0 + arow + 64) * Kd + achk;
    const bf16* gAl0 = Al + Aoff + (size_t)(row0 + arow) * Kd + achk;
    const bf16* gAl1 = Al + Aoff + (size_t)(row0 + arow + 64) * Kd + achk;
    const bf16* gWh0 = Wh + (size_t)(col0 + arow) * Kd + achk;
    const bf16* gWh1 = Wh + (size_t)(col0 + arow + 64) * Kd + achk;
    const bf16* gWl0 = Wl + (size_t)(col0 + arow) * Kd + achk;
    const bf16* gWl1 = Wl + (size_t)(col0 + arow + 64) * Kd + achk;

    float acc[2][8][4];
#pragma unroll
    for (int mt = 0; mt < 2; mt++)
#pragma unroll
        for (int nt = 0; nt < 8; nt++)
#pragma unroll
            for (int i = 0; i < 4; i++) acc[mt][nt][i] = 0.f;

    LOAD_A_ASYNC(0, 0)
    LOAD_W_ASYNC(0, 0)
    CP_COMMIT();
    CP_WAIT0();
    __syncthreads();

    int buf = 0;
    for (int k0 = 32; k0 < Kd; k0 += 32) {
        LOAD_A_ASYNC(buf ^ 1, k0)
        LOAD_W_ASYNC(buf ^ 1, k0)
        CP_COMMIT();
        TC_COMPUTE(buf)
        CP_WAIT0();
        __syncthreads();
        buf ^= 1;
    }
    TC_COMPUTE(buf)
    TC_EPILOGUE
}

// ============ split-K GEMM partials: part[kc] = A @ W^T (chunk kc) =========
// qmode: A row m -> ((m>>4)*KK + (m&15))  (first 16 rows of each batch of g_x)
#define SKP 68

#define SK_STS(BUF)                                                       \
    {                                                                     \
        float* as = As[BUF]; float* bs = Bs[BUF];                         \
        as[(lc + 0) * SKP + lr] = av.x;                                   \
        as[(lc + 1) * SKP + lr] = av.y;                                   \
        as[(lc + 2) * SKP + lr] = av.z;                                   \
        as[(lc + 3) * SKP + lr] = av.w;                                   \
        bs[(lc + 0) * SKP + lr] = bv.x;                                   \
        bs[(lc + 1) * SKP + lr] = bv.y;                                   \
        bs[(lc + 2) * SKP + lr] = bv.z;                                   \
        bs[(lc + 3) * SKP + lr] = bv.w;                                   \
    }

#define SK_COMPUTE(BUF)                                                   \
    _Pragma("unroll")                                                     \
    for (int k = 0; k < 16; k++) {                                        \
        float a[4], bb[4];                                                \
        *(float4*)a  = *(const float4*)&As[BUF][k * SKP + ty4];           \
        *(float4*)bb = *(const float4*)&Bs[BUF][k * SKP + tx4];           \
        _Pragma("unroll")                                                 \
        for (int i = 0; i < 4; i++)                                       \
            _Pragma("unroll")                                             \
            for (int j = 0; j < 4; j++)                                   \
                acc[i][j] = fmaf(a[i], bb[j], acc[i][j]);                 \
    }

__global__ void __launch_bounds__(256)
gemm_splitk(const float* __restrict__ A, const float* __restrict__ W,
            float* __restrict__ part, int qmode) {
    const int kc = blockIdx.z;
    const int row0 = blockIdx.y * 64, col0 = blockIdx.x * 64;
    const int tid = threadIdx.x;
    const int tx4 = (tid & 15) * 4, ty4 = (tid >> 4) * 4;
    const int lr = tid >> 2, lc = (tid & 3) << 2;

    __shared__ __align__(16) float As[2][16 * SKP];
    __shared__ __align__(16) float Bs[2][16 * SKP];

    long long arow = row0 + lr;
    if (qmode) arow = (arow >> 4) * KK + (arow & 15);
    const float* Ar = A + (size_t)arow * EE + kc * 128 + lc;
    const float* Wr = W + (size_t)(col0 + lr) * EE + kc * 128 + lc;

    float acc[4][4];
#pragma unroll
    for (int i = 0; i < 4; i++)
#pragma unroll
        for (int j = 0; j < 4; j++) acc[i][j] = 0.f;

    float4 av = *(const float4*)(Ar);
    float4 bv = *(const float4*)(Wr);
    SK_STS(0)
    __syncthreads();

    int buf = 0;
#pragma unroll
    for (int k0 = 16; k0 < 128; k0 += 16) {
        av = *(const float4*)(Ar + k0);
        bv = *(const float4*)(Wr + k0);
        SK_COMPUTE(buf)
        SK_STS(buf ^ 1)
        __syncthreads();
        buf ^= 1;
    }
    SK_COMPUTE(buf)

    float* pp = part + (size_t)kc * (BB * TT * EE);
#pragma unroll
    for (int i = 0; i < 4; i++) {
        float4 v;
        v.x = acc[i][0]; v.y = acc[i][1]; v.z = acc[i][2]; v.w = acc[i][3];
        *(float4*)(pp + (size_t)(row0 + ty4 + i) * EE + col0 + tx4) = v;
    }
}

// -------- epi_q: g_q = (sum(part) + bq) / 8 -------------------------------
__global__ void __launch_bounds__(128)
epi_q(const float* __restrict__ bq) {
    const int row = blockIdx.x;
    const int tid = threadIdx.x;
#pragma unroll
    for (int u = 0; u < 4; u++) {
        int e = tid + u * 128;
        size_t o = (size_t)row * EE + e;
        float t = g_part[o] + g_part[o + 1 * BB * TT * EE] +
                  g_part[o + 2 * BB * TT * EE] + g_part[o + 3 * BB * TT * EE];
        g_q[o] = (t + bq[e]) * 0.125f;
    }
}

// -------- attention chunk: partial softmax numerator over 128 keys ---------
__global__ void __launch_bounds__(256)
attn_chunk() {
    const int h = blockIdx.x, b = blockIdx.y, c = blockIdx.z;
    const float* kb = g_kv + (size_t)b * KK * 2 * EE + h * 64;
    const float* vb = kb + EE;

    __shared__ float qs[TT][64];
    __shared__ float ks[CK * 65];
    __shared__ float lg[TT][CK];
    __shared__ float vs[32][68];
    const int tid = threadIdx.x;

    {
        int t = tid >> 4;
        int d = (tid * 4) & 63;
        *(float4*)&qs[t][d] =
            *(const float4*)(g_q + ((size_t)b * TT + t) * EE + h * 64 + d);
    }
    const int vr = tid >> 4, vc = (tid & 15) * 4;
    for (int r0 = 0; r0 < CK; r0 += 16) {
        float4 k4 = *(const float4*)(kb + (size_t)(c * CK + r0 + vr) * (2 * EE) + vc);
        float* kp = &ks[(r0 + vr) * 65 + vc];
        kp[0] = k4.x; kp[1] = k4.y; kp[2] = k4.z; kp[3] = k4.w;
    }
    __syncthreads();

    {
        const int kk = tid & 127, th = tid >> 7;
        float acc[8];
#pragma unroll
        for (int i = 0; i < 8; i++) acc[i] = 0.f;
        const float* kr = &ks[kk * 65];
#pragma unroll 8
        for (int d = 0; d < 64; d++) {
            float kv = kr[d];
#pragma unroll
            for (int i = 0; i < 8; i++)
                acc[i] = fmaf(qs[th * 8 + i][d], kv, acc[i]);
        }
#pragma unroll
        for (int i = 0; i < 8; i++) lg[th * 8 + i][kk] = acc[i];
    }
    __syncthreads();

    const int w = tid >> 5, lane = tid & 31;
    for (int t = w; t < TT; t += 8) {
        float m = -1e30f;
        for (int i = lane; i < CK; i += 32) m = fmaxf(m, lg[t][i]);
#pragma unroll
        for (int o = 16; o > 0; o >>= 1) m = fmaxf(m, __shfl_xor_sync(0xFFFFFFFFu, m, o));
        float ssum = 0.f;
        for (int i = lane; i < CK; i += 32) {
            float e = __expf(lg[t][i] - m);
            lg[t][i] = e; ssum += e;
        }
#pragma unroll
        for (int o = 16; o > 0; o >>= 1) ssum += __shfl_xor_sync(0xFFFFFFFFu, ssum, o);
        if (lane == 0) {
            g_m[((size_t)(c * BB + b) * HH + h) * TT + t] = m;
            g_l[((size_t)(c * BB + b) * HH + h) * TT + t] = ssum;
        }
    }

    const int d = tid & 63, tg = tid >> 6;
    float acc4[4] = {0.f, 0.f, 0.f, 0.f};
    for (int kk0 = 0; kk0 < CK; kk0 += 32) {
        __syncthreads();
        const float* vrow = vb + (size_t)(c * CK + kk0 + vr) * (2 * EE) + vc;
        float4 v0 = *(const float4*)(vrow);
        float4 v1 = *(const float4*)(vrow + (size_t)16 * 2 * EE);
        *(float4*)&vs[vr][vc]      = v0;
        *(float4*)&vs[vr + 16][vc] = v1;
        __syncthreads();
#pragma unroll
        for (int r = 0; r < 32; r++) {
            float v = vs[r][d];
#pragma unroll
            for (int i = 0; i < 4; i++)
                acc4[i] = fmaf(lg[tg + i * 4][kk0 + r], v, acc4[i]);
        }
    }
#pragma unroll
    for (int i = 0; i < 4; i++)
        g_part[((size_t)(c * BB + b) * TT + tg + i * 4) * EE + h * 64 + d] = acc4[i];
}

// -------- attention combine: merge 4 chunks -> g_o ------------------------
__global__ void __launch_bounds__(256)
attn_combine() {
    const int h = blockIdx.x, b = blockIdx.y;
    const int tid = threadIdx.x;
    const int d = tid & 63, tg = tid >> 6;
#pragma unroll
    for (int i = 0; i < 4; i++) {
        const int t = tg + i * 4;
        float m[NC], l[NC];
#pragma unroll
        for (int c = 0; c < NC; c++) {
            m[c] = g_m[((size_t)(c * BB + b) * HH + h) * TT + t];
            l[c] = g_l[((size_t)(c * BB + b) * HH + h) * TT + t];
        }
        float mstar = fmaxf(fmaxf(m[0], m[1]), fmaxf(m[2], m[3]));
        float wgt[NC], denom = 0.f;
#pragma unroll
        for (int c = 0; c < NC; c++) {
            wgt[c] = __expf(m[c] - mstar);
            denom += wgt[c] * l[c];
        }
        float o = 0.f;
#pragma unroll
        for (int c = 0; c < NC; c++)
            o += wgt[c] *
                 g_part[((size_t)(c * BB + b) * TT + t) * EE + h * 64 + d];
        g_o[((size_t)b * TT + t) * EE + h * 64 + d] = o / denom;
    }
}

// -------- epilogue 1: y = sum(part) + bo + x_res ; z = LN(y) --------------
__global__ void __launch_bounds__(128)
epi_ln(const float* __restrict__ bo,
       const float* __restrict__ lng, const float* __restrict__ lnb) {
    const int row = blockIdx.x;
    const int tid = threadIdx.x;
    const float* xres = g_x + ((size_t)(row >> 4) * KK + (row & 15)) * EE;
    float* zr = g_z + (size_t)row * EE;
    __shared__ float red[4];

    float v[4];
#pragma unroll
    for (int u = 0; u < 4; u++) {
        int e = tid + u * 128;
        size_t o = (size_t)row * EE + e;
        float s = g_part[o] + g_part[o + 1 * BB * TT * EE] +
                  g_part[o + 2 * BB * TT * EE] + g_part[o + 3 * BB * TT * EE];
        v[u] = s + bo[e] + xres[e];
    }

    float s = v[0] + v[1] + v[2] + v[3];
#pragma unroll
    for (int o = 16; o > 0; o >>= 1) s += __shfl_xor_sync(0xFFFFFFFFu, s, o);
    if ((tid & 31) == 0) red[tid >> 5] = s;
    __syncthreads();
    const float mu = (red[0] + red[1] + red[2] + red[3]) / EE;
    __syncthreads();

    float q = 0.f;
#pragma unroll
    for (int u = 0; u < 4; u++) { float dlt = v[u] - mu; q += dlt * dlt; }
#pragma unroll
    for (int o = 16; o > 0; o >>= 1) q += __shfl_xor_sync(0xFFFFFFFFu, q, o);
    if ((tid & 31) == 0) red[tid >> 5] = q;
    __syncthreads();
    const float rstd = rsqrtf((red[0] + red[1] + red[2] + red[3]) / EE + 1e-5f);

#pragma unroll
    for (int u = 0; u < 4; u++) {
        int e = tid + u * 128;
        zr[e] = (v[u] - mu) * rstd * lng[e] + lnb[e];
    }
}

// -------- epilogue 2: out = z + gelu(sum(part) + bf) ----------------------
__global__ void __launch_bounds__(128)
epi_ffn(const float* __restrict__ bf, float* __restrict__ out) {
    const int row = blockIdx.x;
    const int tid = threadIdx.x;
    const float* zr = g_z + (size_t)row * EE;
    float* outp = out + (size_t)row * EE;
#pragma unroll
    for (int u = 0; u < 4; u++) {
        int e = tid + u * 128;
        size_t o = (size_t)row * EE + e;
        float t = g_part[o] + g_part[o + 1 * BB * TT * EE] +
                  g_part[o + 2 * BB * TT * EE] + g_part[o + 3 * BB * TT * EE] +
                  bf[e];
        float g = 0.5f * t * (1.f + erff(t * 0.70710678118654752f));
        outp[e] = zr[e] + g;
    }
}

// ---------------- launch ----------------
extern "C" void kernel_launch(void* const* d_in, const int* in_sizes, int n_in,
                              void* d_out, int out_size) {
    (void)in_sizes; (void)n_in; (void)out_size;
    const float* feats  = (const float*)d_in[0];
    const float* scores = (const float*)d_in[1];
    const float* proj_w = (const float*)d_in[2];
    const float* proj_b = (const float*)d_in[3];
    const float* in_w   = (const float*)d_in[4];
    const float* in_b   = (const float*)d_in[5];
    const float* out_w  = (const float*)d_in[6];
    const float* out_b  = (const float*)d_in[7];
    const float* ln_g   = (const float*)d_in[8];
    const float* ln_b   = (const float*)d_in[9];
    const float* ffn_w  = (const float*)d_in[10];
    const float* ffn_b  = (const float*)d_in[11];
    float* out = (float*)d_out;

    float *px, *pkv, *po, *pz, *ppart;
    bf16 *pxh, *pxl, *pwph, *pwpl, *pwkh, *pwkl;
    int* pidx;
    cudaGetSymbolAddress((void**)&px,    g_x);
    cudaGetSymbolAddress((void**)&pkv,   g_kv);
    cudaGetSymbolAddress((void**)&po,    g_o);
    cudaGetSymbolAddress((void**)&pz,    g_z);
    cudaGetSymbolAddress((void**)&ppart, g_part);
    cudaGetSymbolAddress((void**)&pidx,  g_idx);
    cudaGetSymbolAddress((void**)&pxh,   g_xh);
    cudaGetSymbolAddress((void**)&pxl,   g_xl);
    cudaGetSymbolAddress((void**)&pwph,  g_wph);
    cudaGetSymbolAddress((void**)&pwpl,  g_wpl);
    cudaGetSymbolAddress((void**)&pwkh,  g_wkh);
    cudaGetSymbolAddress((void**)&pwkl,  g_wkl);

    static int smem_set = 0;
    if (!smem_set) {
        cudaFuncSetAttribute(topk_kernel,
                             cudaFuncAttributeMaxDynamicSharedMemorySize,
                             NN * (int)sizeof(unsigned));
        cudaFuncSetAttribute(gemm_tc_f32a,
                             cudaFuncAttributeMaxDynamicSharedMemorySize,
                             TC_SMEM);
        cudaFuncSetAttribute(gemm_tc_bf16a,
                             cudaFuncAttributeMaxDynamicSharedMemorySize,
                             TC_SMEM);
        smem_set = 1;
    }

    // 1: weight split (independent of topk)
    conv_w_all<<<3 * EE, 128>>>(proj_w, in_w + EE * EE);
    // 2: top-k
    topk_kernel<<<BB, 1024, NN * sizeof(unsigned)>>>(scores);
    // 3: x = feats[idx] @ proj_w^T + proj_b  (fused gather+split; emits x h/l)
    gemm_tc_f32a<<<dim3(EE / 128, KK / 128, BB), 256, TC_SMEM>>>(
        pwph, pwpl, proj_b, px, (long long)KK * EE, DD, pidx, feats, pxh, pxl);
    // 4: kv = x @ [Wk;Wv]^T + b  (all-cp.async)   <-- profiled launch
    gemm_tc_bf16a<<<dim3(2 * EE / 128, KK / 128, BB), 256, TC_SMEM>>>(
        pxh, pxl, (long long)KK * EE, pwkh, pwkl, in_b + EE, pkv,
        (long long)KK * 2 * EE, EE);

    // q = (x[:, :16] @ Wq^T + bq)/8  via split-K + epilogue
    gemm_splitk<<<dim3(EE / 64, (BB * TT) / 64, 4), 256>>>(px, in_w, ppart, 1);
    epi_q<<<BB * TT, 128>>>(in_b);

    // attention: chunked flash partials, combine
    attn_chunk<<<dim3(HH, BB, NC), 256>>>();
    attn_combine<<<dim3(HH, BB), 256>>>();

    // out_proj split-K partials, then fused (sum + bias + residual + LN)
    gemm_splitk<<<dim3(EE / 64, (BB * TT) / 64, 4), 256>>>(po, out_w, ppart, 0);
    epi_ln<<<BB * TT, 128>>>(out_b, ln_g, ln_b);

    // FFN split-K partials, then fused (sum + bias + GELU + residual)
    gemm_splitk<<<dim3(EE / 64, (BB * TT) / 64, 4), 256>>>(pz, ffn_w, ppart, 0);
    epi_ffn<<<BB * TT, 128>>>(ffn_b, out);
}

// round 15
// speedup vs baseline: 1.2536x; 1.2536x over previous
#include <cuda_runtime.h>
#include <cuda_bf16.h>
#include <cstdint>
#include <math.h>

#define BB 16
#define NN 32768
#define DD 256
#define EE 512
#define HH 8
#define KK 512
#define TT 16
#define NC 4      // attention key chunks
#define CK 128    // keys per chunk

typedef __nv_bfloat16 bf16;

// ---------------- device scratch (no allocations allowed) ----------------
__device__ float g_x[BB * TT * EE];          // x for the 16 live rows/batch
__device__ bf16  g_wfh[2 * EE * DD];         // fused kv weight hi/lo [1024x256]
__device__ bf16  g_wfl[2 * EE * DD];
__device__ float g_bf[2 * EE];               // fused kv bias
__device__ float g_kv[BB * KK * 2 * EE];     // k|v concat fp32
__device__ float g_q[BB * TT * EE];          // scaled q
__device__ float g_o[BB * TT * EE];          // attn out
__device__ float g_z[BB * TT * EE];          // post layernorm
__device__ float g_part[4 * BB * TT * EE];   // split-K / attn partials
__device__ float g_m[NC * BB * HH * TT];
__device__ float g_l[NC * BB * HH * TT];
__device__ int   g_idx[BB * KK];

// order-preserving float->uint key (bigger key == bigger float)
__device__ __forceinline__ unsigned fkey(float f) {
    unsigned u = __float_as_uint(f);
    return (u & 0x80000000u) ? ~u : (u | 0x80000000u);
}

__device__ __forceinline__ void split_bf16(float f, bf16& h, bf16& l) {
    h = __float2bfloat16(f);
    l = __float2bfloat16(f - __bfloat162float(h));
}

__device__ __forceinline__ uint32_t pk2(bf16 a, bf16 b) {
    return (uint32_t)__bfloat16_as_ushort(a) |
           ((uint32_t)__bfloat16_as_ushort(b) << 16);
}

// split 8 floats (two float4) into packed hi uint4 / lo uint4
__device__ __forceinline__ void pack8(float4 a, float4 b, uint4& h, uint4& l) {
    bf16 h0, l0, h1, l1;
    split_bf16(a.x, h0, l0); split_bf16(a.y, h1, l1);
    h.x = pk2(h0, h1); l.x = pk2(l0, l1);
    split_bf16(a.z, h0, l0); split_bf16(a.w, h1, l1);
    h.y = pk2(h0, h1); l.y = pk2(l0, l1);
    split_bf16(b.x, h0, l0); split_bf16(b.y, h1, l1);
    h.z = pk2(h0, h1); l.z = pk2(l0, l1);
    split_bf16(b.z, h0, l0); split_bf16(b.w, h1, l1);
    h.w = pk2(h0, h1); l.w = pk2(l0, l1);
}

__device__ __forceinline__ void cp16(uint32_t s, const void* g) {
    asm volatile("cp.async.cg.shared.global [%0], [%1], 16;" :: "r"(s), "l"(g));
}

// ---------------- top-K: smem-resident keys, radix select + bitonic sort ----
extern __shared__ unsigned skeys[];   // NN unsigned = 128 KB dynamic smem

__global__ void __launch_bounds__(1024) topk_kernel(const float* __restrict__ scores) {
    const int b = blockIdx.x;
    const float* s = scores + (size_t)b * NN;
    const int tid = threadIdx.x;

    __shared__ unsigned hist[256];
    __shared__ unsigned sh_prefix, sh_mask, sh_remk;
    __shared__ int sh_cntgt, sh_cnteq;
    __shared__ unsigned long long sel[512];
    __shared__ int eq[1024];

    if (tid == 0) { sh_prefix = 0u; sh_mask = 0u; sh_remk = KK; }
    if (tid < 256) hist[tid] = 0u;
    __syncthreads();

    for (int i = tid; i < NN; i += 1024) {
        unsigned k = fkey(__ldg(&s[i]));
        skeys[i] = k;
        atomicAdd(&hist[k >> 24], 1u);
    }
    __syncthreads();

    for (int pass = 0; pass < 4; pass++) {
        const int shift = 24 - pass * 8;
        if (tid == 0) {
            unsigned remk = sh_remk, acc = 0u;
            int d;
            for (d = 255; d >= 0; d--) {
                if (acc + hist[d] >= remk) break;
                acc += hist[d];
            }
            sh_remk  = remk - acc;
            sh_prefix = sh_prefix | ((unsigned)d << shift);
            sh_mask   = sh_mask | (0xFFu << shift);
            sh_cntgt = 0; sh_cnteq = 0;
        }
        __syncthreads();
        if (pass == 3) break;
        if (tid < 256) hist[tid] = 0u;
        __syncthreads();
        const unsigned prefix = sh_prefix, mask = sh_mask;
        const int nshift = shift - 8;
        for (int i = tid; i < NN; i += 1024) {
            unsigned k = skeys[i];
            if ((k & mask) == prefix) atomicAdd(&hist[(k >> nshift) & 255u], 1u);
        }
        __syncthreads();
    }

    const unsigned Tkey = sh_prefix;
    const int remk = (int)sh_remk;

    for (int i = tid; i < NN; i += 1024) {
        unsigned k = skeys[i];
        if (k > Tkey) {
            int p = atomicAdd(&sh_cntgt, 1);
            sel[p] = ((unsigned long long)k << 32) | (unsigned)(0xFFFFFFFFu - (unsigned)i);
        } else if (k == Tkey) {
            int p = atomicAdd(&sh_cnteq, 1);
            if (p < 1024) eq[p] = i;
        }
    }
    __syncthreads();
    const int cntgt = sh_cntgt;
    const int cnteq = min(sh_cnteq, 1024);

    if (tid >= cnteq) eq[tid] = 0x7FFFFFFF;
    __syncthreads();
    for (unsigned k = 2; k <= 1024; k <<= 1)
        for (unsigned j = k >> 1; j > 0; j >>= 1) {
            unsigned i = tid, ixj = i ^ j;
            if (ixj > i) {
                int a = eq[i], c = eq[ixj];
                bool up = ((i & k) == 0);
                if ((a > c) == up) { eq[i] = c; eq[ixj] = a; }
            }
            __syncthreads();
        }
    for (int jj = tid; jj < remk; jj += 1024)
        sel[cntgt + jj] = ((unsigned long long)Tkey << 32) |
                          (unsigned)(0xFFFFFFFFu - (unsigned)eq[jj]);
    __syncthreads();

    for (unsigned k = 2; k <= 512; k <<= 1)
        for (unsigned j = k >> 1; j > 0; j >>= 1) {
            if (tid < 512) {
                unsigned i = tid, ixj = i ^ j;
                if (ixj > i) {
                    unsigned long long a = sel[i], c = sel[ixj];
                    bool up = ((i & k) == 0);
                    if ((a > c) == up) { sel[i] = c; sel[ixj] = a; }
                }
            }
            __syncthreads();
        }
    if (tid < 512)
        g_idx[b * KK + tid] =
            (int)(0xFFFFFFFFu - (unsigned)(sel[511 - tid] & 0xFFFFFFFFull));
}

// -------- Wfuse = Wkv @ Wp  [1024 x 256], split to bf16 hi/lo --------------
__global__ void __launch_bounds__(256)
wfuse_kernel(const float* __restrict__ Wkv, const float* __restrict__ Wp) {
    const int row0 = blockIdx.y * 64;   // over 1024 (kv out dim)
    const int col0 = blockIdx.x * 64;   // over 256 (feat dim)
    const int tid = threadIdx.x;
    const int tx4 = (tid & 15) * 4, ty4 = (tid >> 4) * 4;
    __shared__ float As[16][68];
    __shared__ float Bs[16][68];
    const int ar = tid >> 2, ac = (tid & 3) << 2;    // A loader
    const int br = tid >> 4, bc = (tid & 15) << 2;   // B loader

    float acc[4][4];
#pragma unroll
    for (int i = 0; i < 4; i++)
#pragma unroll
        for (int j = 0; j < 4; j++) acc[i][j] = 0.f;

    for (int k0 = 0; k0 < EE; k0 += 16) {
        float4 av = *(const float4*)(Wkv + (size_t)(row0 + ar) * EE + k0 + ac);
        float4 bv = *(const float4*)(Wp + (size_t)(k0 + br) * DD + col0 + bc);
        __syncthreads();
        As[ac + 0][ar] = av.x; As[ac + 1][ar] = av.y;
        As[ac + 2][ar] = av.z; As[ac + 3][ar] = av.w;
        *(float4*)&Bs[br][bc] = bv;
        __syncthreads();
#pragma unroll
        for (int k = 0; k < 16; k++) {
            float a[4], bb[4];
            *(float4*)a  = *(const float4*)&As[k][ty4];
            *(float4*)bb = *(const float4*)&Bs[k][tx4];
#pragma unroll
            for (int i = 0; i < 4; i++)
#pragma unroll
                for (int j = 0; j < 4; j++)
                    acc[i][j] = fmaf(a[i], bb[j], acc[i][j]);
        }
    }
#pragma unroll
    for (int i = 0; i < 4; i++)
#pragma unroll
        for (int j = 0; j < 4; j++) {
            int r = row0 + ty4 + i, c = col0 + tx4 + j;
            bf16 h, l;
            split_bf16(acc[i][j], h, l);
            g_wfh[(size_t)r * DD + c] = h;
            g_wfl[(size_t)r * DD + c] = l;
        }
}

// -------- bias_fuse[n] = Wkv[n] . proj_b + bkv[n] --------------------------
__global__ void __launch_bounds__(128)
bias_fuse_kernel(const float* __restrict__ Wkv, const float* __restrict__ pb,
                 const float* __restrict__ bkv) {
    const int row = blockIdx.x * 4 + (threadIdx.x >> 5);
    const int lane = threadIdx.x & 31;
    float s = 0.f;
    for (int e = lane; e < EE; e += 32)
        s = fmaf(Wkv[(size_t)row * EE + e], pb[e], s);
#pragma unroll
    for (int o = 16; o > 0; o >>= 1) s += __shfl_xor_sync(0xFFFFFFFFu, s, o);
    if (lane == 0) g_bf[row] = s + bkv[row];
}

// ============== tensor-core split-bf16 GEMM (kv from gathered feats) =======
// CTA tile 128x128, warp tile 32x64, mma m16n8k16 x 3 products (hh, hl, lh).
#define AP 40          // smem pitch in bf16 (80B: conflict-free ldmatrix)
#define SA_ELEM (128 * AP)
#define SW_ELEM (128 * AP)
#define TC_SMEM ((2 * SA_ELEM + 2 * SW_ELEM) * 2 * 2)  // 81920 bytes

__device__ __forceinline__ void ldsm4(uint32_t r[4], uint32_t addr) {
    asm volatile("ldmatrix.sync.aligned.m8n8.x4.shared.b16 {%0,%1,%2,%3}, [%4];"
                 : "=r"(r[0]), "=r"(r[1]), "=r"(r[2]), "=r"(r[3]) : "r"(addr));
}
__device__ __forceinline__ void mma_bf16(float c[4], const uint32_t a[4],
                                         uint32_t b0, uint32_t b1) {
    asm volatile(
        "mma.sync.aligned.m16n8k16.row.col.f32.bf16.bf16.f32 "
        "{%0,%1,%2,%3}, {%4,%5,%6,%7}, {%8,%9}, {%0,%1,%2,%3};"
        : "+f"(c[0]), "+f"(c[1]), "+f"(c[2]), "+f"(c[3])
        : "r"(a[0]), "r"(a[1]), "r"(a[2]), "r"(a[3]), "r"(b0), "r"(b1));
}

#define LOAD_A_F32(K0)                                                    \
    {                                                                     \
        float4 x0 = *(const float4*)(gA0 + (K0));                         \
        float4 x1 = *(const float4*)(gA0 + (K0) + 4);                     \
        float4 y0 = *(const float4*)(gA1 + (K0));                         \
        float4 y1 = *(const float4*)(gA1 + (K0) + 4);                     \
        pack8(x0, x1, pAh0, pAl0);                                        \
        pack8(y0, y1, pAh1, pAl1);                                        \
    }

#define LOAD_W_ASYNC(BUF, K0)                                             \
    {                                                                     \
        cp16(baseWh + 2u * ((BUF) * SW_ELEM + arow * AP + achk), gWh0 + (K0)); \
        cp16(baseWh + 2u * ((BUF) * SW_ELEM + (arow + 64) * AP + achk), gWh1 + (K0)); \
        cp16(baseWl + 2u * ((BUF) * SW_ELEM + arow * AP + achk), gWl0 + (K0)); \
        cp16(baseWl + 2u * ((BUF) * SW_ELEM + (arow + 64) * AP + achk), gWl1 + (K0)); \
    }

#define CP_COMMIT() asm volatile("cp.async.commit_group;\n" ::: "memory")
#define CP_WAIT0()  asm volatile("cp.async.wait_group 0;\n" ::: "memory")

#define STS_A(BUF)                                                        \
    {                                                                     \
        *(uint4*)&sAh[(BUF) * SA_ELEM + arow * AP + achk]        = pAh0;  \
        *(uint4*)&sAh[(BUF) * SA_ELEM + (arow + 64) * AP + achk] = pAh1;  \
        *(uint4*)&sAl[(BUF) * SA_ELEM + arow * AP + achk]        = pAl0;  \
        *(uint4*)&sAl[(BUF) * SA_ELEM + (arow + 64) * AP + achk] = pAl1;  \
    }

#define TC_COMPUTE(BUF)                                                   \
    _Pragma("unroll")                                                     \
    for (int ks = 0; ks < 32; ks += 16) {                                 \
        uint32_t ah[2][4], al[2][4];                                      \
        _Pragma("unroll")                                                 \
        for (int mt = 0; mt < 2; mt++) {                                  \
            uint32_t off = 2u * ((BUF) * SA_ELEM + (wm + mt * 16) * AP + aoffA + ks); \
            ldsm4(ah[mt], baseAh + off);                                  \
            ldsm4(al[mt], baseAl + off);                                  \
        }                                                                 \
        _Pragma("unroll")                                                 \
        for (int hf = 0; hf < 2; hf++) {                                  \
            uint32_t wh[2][4], wl[2][4];                                  \
            _Pragma("unroll")                                             \
            for (int np = 0; np < 2; np++) {                              \
                uint32_t off = 2u * ((BUF) * SW_ELEM + (wn + (hf * 2 + np) * 16) * AP + woffW + ks); \
                ldsm4(wh[np], baseWh + off);                              \
                ldsm4(wl[np], baseWl + off);                              \
            }                                                             \
            _Pragma("unroll")                                             \
            for (int mt = 0; mt < 2; mt++)                                \
                _Pragma("unroll")                                         \
                for (int nt = 0; nt < 4; nt++) {                          \
                    uint32_t bh0 = wh[nt >> 1][(nt & 1) * 2];             \
                    uint32_t bh1 = wh[nt >> 1][(nt & 1) * 2 + 1];         \
                    uint32_t bl0 = wl[nt >> 1][(nt & 1) * 2];             \
                    uint32_t bl1 = wl[nt >> 1][(nt & 1) * 2 + 1];         \
                    mma_bf16(acc[mt][hf * 4 + nt], ah[mt], bh0, bh1);     \
                    mma_bf16(acc[mt][hf * 4 + nt], ah[mt], bl0, bl1);     \
                    mma_bf16(acc[mt][hf * 4 + nt], al[mt], bh0, bh1);     \
                }                                                         \
        }                                                                 \
    }

// kv = feats[idx] @ Wfuse^T + bias_fuse   (Kd = 256, N = 1024)
__global__ void __launch_bounds__(256, 2)
gemm_tc_kv(const bf16* __restrict__ Wh, const bf16* __restrict__ Wl,
           const float* __restrict__ bias,
           float* __restrict__ C, long long strideC,
           int Kd,
           const int* __restrict__ idxp, const float* __restrict__ gfeat) {
    extern __shared__ __align__(16) char smraw[];
    bf16* sAh = (bf16*)smraw;
    bf16* sAl = sAh + 2 * SA_ELEM;
    bf16* sWh = sAl + 2 * SA_ELEM;
    bf16* sWl = sWh + 2 * SW_ELEM;
    const int b = blockIdx.z;
    const int row0 = blockIdx.y * 128, col0 = blockIdx.x * 128;
    const int N = gridDim.x * 128;
    const int tid = threadIdx.x;
    const int lane = tid & 31, wid = tid >> 5;
    const int wm = (wid & 3) * 32, wn = (wid >> 2) * 64;
    const uint32_t baseAh = (uint32_t)__cvta_generic_to_shared(sAh);
    const uint32_t baseAl = (uint32_t)__cvta_generic_to_shared(sAl);
    const uint32_t baseWh = (uint32_t)__cvta_generic_to_shared(sWh);
    const uint32_t baseWl = (uint32_t)__cvta_generic_to_shared(sWl);
    const uint32_t aoffA = (lane & 15) * AP + ((lane >> 4) << 3);
    const uint32_t woffW = ((lane & 7) + ((lane & 16) >> 1)) * AP + (lane & 8);
    const int arow = tid >> 2;
    const int achk = (tid & 3) * 8;

    const int* ib = idxp + b * KK;
    const float* gA0 = gfeat + ((size_t)b * NN + ib[row0 + arow]) * Kd + achk;
    const float* gA1 = gfeat + ((size_t)b * NN + ib[row0 + arow + 64]) * Kd + achk;
    const bf16* gWh0 = Wh + (size_t)(col0 + arow) * Kd + achk;
    const bf16* gWh1 = Wh + (size_t)(col0 + arow + 64) * Kd + achk;
    const bf16* gWl0 = Wl + (size_t)(col0 + arow) * Kd + achk;
    const bf16* gWl1 = Wl + (size_t)(col0 + arow + 64) * Kd + achk;

    float acc[2][8][4];
#pragma unroll
    for (int mt = 0; mt < 2; mt++)
#pragma unroll
        for (int nt = 0; nt < 8; nt++)
#pragma unroll
            for (int i = 0; i < 4; i++) acc[mt][nt][i] = 0.f;

    uint4 pAh0, pAh1, pAl0, pAl1;
    LOAD_A_F32(0)
    LOAD_W_ASYNC(0, 0)
    CP_COMMIT();
    STS_A(0)
    CP_WAIT0();
    __syncthreads();

    int buf = 0;
    for (int k0 = 32; k0 < Kd; k0 += 32) {
        LOAD_A_F32(k0)
        LOAD_W_ASYNC(buf ^ 1, k0)
        CP_COMMIT();
        TC_COMPUTE(buf)
        STS_A(buf ^ 1)
        CP_WAIT0();
        __syncthreads();
        buf ^= 1;
    }
    TC_COMPUTE(buf)

    const int g = lane >> 2, tq = (lane & 3) * 2;
#pragma unroll
    for (int mt = 0; mt < 2; mt++)
#pragma unroll
        for (int nt = 0; nt < 8; nt++) {
            int r = row0 + wm + mt * 16 + g;
            int cc = col0 + wn + nt * 8 + tq;
            float b0 = bias[cc], b1 = bias[cc + 1];
            size_t i0 = (size_t)((long long)b * strideC) + (size_t)r * N + cc;
            size_t i1 = (size_t)((long long)b * strideC) + (size_t)(r + 8) * N + cc;
            *(float2*)(C + i0) = make_float2(acc[mt][nt][0] + b0, acc[mt][nt][1] + b1);
            *(float2*)(C + i1) = make_float2(acc[mt][nt][2] + b0, acc[mt][nt][3] + b1);
        }
}

// ============ split-K GEMM partials: part[kc] = A @ W^T (chunk kc) =========
// idxp != null: A row m -> gfeat row (b*NN + idx[b*KK + (m&15)]), b = m>>4.
#define SKP 68

#define SK_STS(BUF)                                                       \
    {                                                                     \
        float* as = As[BUF]; float* bs = Bs[BUF];                         \
        as[(lc + 0) * SKP + lr] = av.x;                                   \
        as[(lc + 1) * SKP + lr] = av.y;                                   \
        as[(lc + 2) * SKP + lr] = av.z;                                   \
        as[(lc + 3) * SKP + lr] = av.w;                                   \
        bs[(lc + 0) * SKP + lr] = bv.x;                                   \
        bs[(lc + 1) * SKP + lr] = bv.y;                                   \
        bs[(lc + 2) * SKP + lr] = bv.z;                                   \
        bs[(lc + 3) * SKP + lr] = bv.w;                                   \
    }

#define SK_COMPUTE(BUF)                                                   \
    _Pragma("unroll")                                                     \
    for (int k = 0; k < 16; k++) {                                        \
        float a[4], bb[4];                                                \
        *(float4*)a  = *(const float4*)&As[BUF][k * SKP + ty4];           \
        *(float4*)bb = *(const float4*)&Bs[BUF][k * SKP + tx4];           \
        _Pragma("unroll")                                                 \
        for (int i = 0; i < 4; i++)                                       \
            _Pragma("unroll")                                             \
            for (int j = 0; j < 4; j++)                                   \
                acc[i][j] = fmaf(a[i], bb[j], acc[i][j]);                 \
    }

__global__ void __launch_bounds__(256)
gemm_splitk(const float* __restrict__ A, int astride,
            const int* __restrict__ idxp,
            const float* __restrict__ W, int wstride,
            float* __restrict__ part) {
    const int kc = blockIdx.z;
    const int row0 = blockIdx.y * 64, col0 = blockIdx.x * 64;
    const int tid = threadIdx.x;
    const int tx4 = (tid & 15) * 4, ty4 = (tid >> 4) * 4;
    const int lr = tid >> 2, lc = (tid & 3) << 2;

    __shared__ __align__(16) float As[2][16 * SKP];
    __shared__ __align__(16) float Bs[2][16 * SKP];

    const int m = row0 + lr;
    size_t arow;
    if (idxp) {
        int bb = m >> 4;
        arow = (size_t)bb * NN + idxp[bb * KK + (m & 15)];
    } else {
        arow = (size_t)m;
    }
    const float* Ar = A + arow * astride + kc * 128 + lc;
    const float* Wr = W + (size_t)(col0 + lr) * wstride + kc * 128 + lc;

    float acc[4][4];
#pragma unroll
    for (int i = 0; i < 4; i++)
#pragma unroll
        for (int j = 0; j < 4; j++) acc[i][j] = 0.f;

    float4 av = *(const float4*)(Ar);
    float4 bv = *(const float4*)(Wr);
    SK_STS(0)
    __syncthreads();

    int buf = 0;
#pragma unroll
    for (int k0 = 16; k0 < 128; k0 += 16) {
        av = *(const float4*)(Ar + k0);
        bv = *(const float4*)(Wr + k0);
        SK_COMPUTE(buf)
        SK_STS(buf ^ 1)
        __syncthreads();
        buf ^= 1;
    }
    SK_COMPUTE(buf)

    float* pp = part + (size_t)kc * (BB * TT * EE);
#pragma unroll
    for (int i = 0; i < 4; i++) {
        float4 v;
        v.x = acc[i][0]; v.y = acc[i][1]; v.z = acc[i][2]; v.w = acc[i][3];
        *(float4*)(pp + (size_t)(row0 + ty4 + i) * EE + col0 + tx4) = v;
    }
}

// -------- epi_x16: g_x = part0 + part1 + proj_b  (K=256, 2 chunks) --------
__global__ void __launch_bounds__(128)
epi_x16(const float* __restrict__ pb) {
    const int row = blockIdx.x;
    const int tid = threadIdx.x;
#pragma unroll
    for (int u = 0; u < 4; u++) {
        int e = tid + u * 128;
        size_t o = (size_t)row * EE + e;
        g_x[o] = g_part[o] + g_part[o + 1 * BB * TT * EE] + pb[e];
    }
}

// -------- epi_q: g_q = (sum of 4 partials + bq) / 8 -----------------------
__global__ void __launch_bounds__(128)
epi_q(const float* __restrict__ bq) {
    const int row = blockIdx.x;
    const int tid = threadIdx.x;
#pragma unroll
    for (int u = 0; u < 4; u++) {
        int e = tid + u * 128;
        size_t o = (size_t)row * EE + e;
        float t = g_part[o] + g_part[o + 1 * BB * TT * EE] +
                  g_part[o + 2 * BB * TT * EE] + g_part[o + 3 * BB * TT * EE];
        g_q[o] = (t + bq[e]) * 0.125f;
    }
}

// -------- attention chunk: partial softmax numerator over 128 keys ---------
__global__ void __launch_bounds__(256)
attn_chunk() {
    const int h = blockIdx.x, b = blockIdx.y, c = blockIdx.z;
    const float* kb = g_kv + (size_t)b * KK * 2 * EE + h * 64;
    const float* vb = kb + EE;

    __shared__ float qs[TT][64];
    __shared__ float ks[CK * 65];
    __shared__ float lg[TT][CK];
    __shared__ float vs[32][68];
    const int tid = threadIdx.x;

    {
        int t = tid >> 4;
        int d = (tid * 4) & 63;
        *(float4*)&qs[t][d] =
            *(const float4*)(g_q + ((size_t)b * TT + t) * EE + h * 64 + d);
    }
    const int vr = tid >> 4, vc = (tid & 15) * 4;
    for (int r0 = 0; r0 < CK; r0 += 16) {
        float4 k4 = *(const float4*)(kb + (size_t)(c * CK + r0 + vr) * (2 * EE) + vc);
        float* kp = &ks[(r0 + vr) * 65 + vc];
        kp[0] = k4.x; kp[1] = k4.y; kp[2] = k4.z; kp[3] = k4.w;
    }
    __syncthreads();

    {
        const int kk = tid & 127, th = tid >> 7;
        float acc[8];
#pragma unroll
        for (int i = 0; i < 8; i++) acc[i] = 0.f;
        const float* kr = &ks[kk * 65];
#pragma unroll 8
        for (int d = 0; d < 64; d++) {
            float kv = kr[d];
#pragma unroll
            for (int i = 0; i < 8; i++)
                acc[i] = fmaf(qs[th * 8 + i][d], kv, acc[i]);
        }
#pragma unroll
        for (int i = 0; i < 8; i++) lg[th * 8 + i][kk] = acc[i];
    }
    __syncthreads();

    const int w = tid >> 5, lane = tid & 31;
    for (int t = w; t < TT; t += 8) {
        float m = -1e30f;
        for (int i = lane; i < CK; i += 32) m = fmaxf(m, lg[t][i]);
#pragma unroll
        for (int o = 16; o > 0; o >>= 1) m = fmaxf(m, __shfl_xor_sync(0xFFFFFFFFu, m, o));
        float ssum = 0.f;
        for (int i = lane; i < CK; i += 32) {
            float e = __expf(lg[t][i] - m);
            lg[t][i] = e; ssum += e;
        }
#pragma unroll
        for (int o = 16; o > 0; o >>= 1) ssum += __shfl_xor_sync(0xFFFFFFFFu, ssum, o);
        if (lane == 0) {
            g_m[((size_t)(c * BB + b) * HH + h) * TT + t] = m;
            g_l[((size_t)(c * BB + b) * HH + h) * TT + t] = ssum;
        }
    }

    const int d = tid & 63, tg = tid >> 6;
    float acc4[4] = {0.f, 0.f, 0.f, 0.f};
    for (int kk0 = 0; kk0 < CK; kk0 += 32) {
        __syncthreads();
        const float* vrow = vb + (size_t)(c * CK + kk0 + vr) * (2 * EE) + vc;
        float4 v0 = *(const float4*)(vrow);
        float4 v1 = *(const float4*)(vrow + (size_t)16 * 2 * EE);
        *(float4*)&vs[vr][vc]      = v0;
        *(float4*)&vs[vr + 16][vc] = v1;
        __syncthreads();
#pragma unroll
        for (int r = 0; r < 32; r++) {
            float v = vs[r][d];
#pragma unroll
            for (int i = 0; i < 4; i++)
                acc4[i] = fmaf(lg[tg + i * 4][kk0 + r], v, acc4[i]);
        }
    }
#pragma unroll
    for (int i = 0; i < 4; i++)
        g_part[((size_t)(c * BB + b) * TT + tg + i * 4) * EE + h * 64 + d] = acc4[i];
}

// -------- attention combine: merge 4 chunks -> g_o ------------------------
__global__ void __launch_bounds__(256)
attn_combine() {
    const int h = blockIdx.x, b = blockIdx.y;
    const int tid = threadIdx.x;
    const int d = tid & 63, tg = tid >> 6;
#pragma unroll
    for (int i = 0; i < 4; i++) {
        const int t = tg + i * 4;
        float m[NC], l[NC];
#pragma unroll
        for (int c = 0; c < NC; c++) {
            m[c] = g_m[((size_t)(c * BB + b) * HH + h) * TT + t];
            l[c] = g_l[((size_t)(c * BB + b) * HH + h) * TT + t];
        }
        float mstar = fmaxf(fmaxf(m[0], m[1]), fmaxf(m[2], m[3]));
        float wgt[NC], denom = 0.f;
#pragma unroll
        for (int c = 0; c < NC; c++) {
            wgt[c] = __expf(m[c] - mstar);
            denom += wgt[c] * l[c];
        }
        float o = 0.f;
#pragma unroll
        for (int c = 0; c < NC; c++)
            o += wgt[c] *
                 g_part[((size_t)(c * BB + b) * TT + t) * EE + h * 64 + d];
        g_o[((size_t)b * TT + t) * EE + h * 64 + d] = o / denom;
    }
}

// -------- epilogue 1: y = sum(part) + bo + x_res ; z = LN(y) --------------
__global__ void __launch_bounds__(128)
epi_ln(const float* __restrict__ bo,
       const float* __restrict__ lng, const float* __restrict__ lnb) {
    const int row = blockIdx.x;
    const int tid = threadIdx.x;
    const float* xres = g_x + (size_t)row * EE;
    float* zr = g_z + (size_t)row * EE;
    __shared__ float red[4];

    float v[4];
#pragma unroll
    for (int u = 0; u < 4; u++) {
        int e = tid + u * 128;
        size_t o = (size_t)row * EE + e;
        float s = g_part[o] + g_part[o + 1 * BB * TT * EE] +
                  g_part[o + 2 * BB * TT * EE] + g_part[o + 3 * BB * TT * EE];
        v[u] = s + bo[e] + xres[e];
    }

    float s = v[0] + v[1] + v[2] + v[3];
#pragma unroll
    for (int o = 16; o > 0; o >>= 1) s += __shfl_xor_sync(0xFFFFFFFFu, s, o);
    if ((tid & 31) == 0) red[tid >> 5] = s;
    __syncthreads();
    const float mu = (red[0] + red[1] + red[2] + red[3]) / EE;
    __syncthreads();

    float q = 0.f;
#pragma unroll
    for (int u = 0; u < 4; u++) { float dlt = v[u] - mu; q += dlt * dlt; }
#pragma unroll
    for (int o = 16; o > 0; o >>= 1) q += __shfl_xor_sync(0xFFFFFFFFu, q, o);
    if ((tid & 31) == 0) red[tid >> 5] = q;
    __syncthreads();
    const float rstd = rsqrtf((red[0] + red[1] + red[2] + red[3]) / EE + 1e-5f);

#pragma unroll
    for (int u = 0; u < 4; u++) {
        int e = tid + u * 128;
        zr[e] = (v[u] - mu) * rstd * lng[e] + lnb[e];
    }
}

// -------- epilogue 2: out = z + gelu(sum(part) + bf) ----------------------
__global__ void __launch_bounds__(128)
epi_ffn(const float* __restrict__ bf, float* __restrict__ out) {
    const int row = blockIdx.x;
    const int tid = threadIdx.x;
    const float* zr = g_z + (size_t)row * EE;
    float* outp = out + (size_t)row * EE;
#pragma unroll
    for (int u = 0; u < 4; u++) {
        int e = tid + u * 128;
        size_t o = (size_t)row * EE + e;
        float t = g_part[o] + g_part[o + 1 * BB * TT * EE] +
                  g_part[o + 2 * BB * TT * EE] + g_part[o + 3 * BB * TT * EE] +
                  bf[e];
        float g = 0.5f * t * (1.f + erff(t * 0.70710678118654752f));
        outp[e] = zr[e] + g;
    }
}

// ---------------- launch ----------------
extern "C" void kernel_launch(void* const* d_in, const int* in_sizes, int n_in,
                              void* d_out, int out_size) {
    (void)in_sizes; (void)n_in; (void)out_size;
    const float* feats  = (const float*)d_in[0];
    const float* scores = (const float*)d_in[1];
    const float* proj_w = (const float*)d_in[2];
    const float* proj_b = (const float*)d_in[3];
    const float* in_w   = (const float*)d_in[4];
    const float* in_b   = (const float*)d_in[5];
    const float* out_w  = (const float*)d_in[6];
    const float* out_b  = (const float*)d_in[7];
    const float* ln_g   = (const float*)d_in[8];
    const float* ln_b   = (const float*)d_in[9];
    const float* ffn_w  = (const float*)d_in[10];
    const float* ffn_b  = (const float*)d_in[11];
    float* out = (float*)d_out;

    float *px, *pkv, *po, *pz, *ppart, *pbf;
    bf16 *pwfh, *pwfl;
    int* pidx;
    cudaGetSymbolAddress((void**)&px,    g_x);
    cudaGetSymbolAddress((void**)&pkv,   g_kv);
    cudaGetSymbolAddress((void**)&po,    g_o);
    cudaGetSymbolAddress((void**)&pz,    g_z);
    cudaGetSymbolAddress((void**)&ppart, g_part);
    cudaGetSymbolAddress((void**)&pidx,  g_idx);
    cudaGetSymbolAddress((void**)&pwfh,  g_wfh);
    cudaGetSymbolAddress((void**)&pwfl,  g_wfl);
    cudaGetSymbolAddress((void**)&pbf,   g_bf);

    static int smem_set = 0;
    if (!smem_set) {
        cudaFuncSetAttribute(topk_kernel,
                             cudaFuncAttributeMaxDynamicSharedMemorySize,
                             NN * (int)sizeof(unsigned));
        cudaFuncSetAttribute(gemm_tc_kv,
                             cudaFuncAttributeMaxDynamicSharedMemorySize,
                             TC_SMEM);
        smem_set = 1;
    }

    // 1: fused kv weight  Wfuse = Wkv @ Wp  (split bf16 h/l)
    wfuse_kernel<<<dim3(DD / 64, 2 * EE / 64), 256>>>(in_w + EE * EE, proj_w);
    // 2: fused kv bias
    bias_fuse_kernel<<<2 * EE / 4, 128>>>(in_w + EE * EE, proj_b, in_b + EE);
    // 3: top-k
    topk_kernel<<<BB, 1024, NN * sizeof(unsigned)>>>(scores);
    // 4: kv = feats[idx] @ Wfuse^T + bias_fuse   <-- profiled launch
    gemm_tc_kv<<<dim3(2 * EE / 128, KK / 128, BB), 256, TC_SMEM>>>(
        pwfh, pwfl, pbf, pkv, (long long)KK * 2 * EE, DD, pidx, feats);

    // x16 = feats[idx[:16]] @ Wp^T + pb  (K=256 -> 2 chunks)
    gemm_splitk<<<dim3(EE / 64, (BB * TT) / 64, 2), 256>>>(
        feats, DD, pidx, proj_w, DD, ppart);
    epi_x16<<<BB * TT, 128>>>(proj_b);

    // q = (x16 @ Wq^T + bq)/8  (K=512 -> 4 chunks)
    gemm_splitk<<<dim3(EE / 64, (BB * TT) / 64, 4), 256>>>(
        px, EE, nullptr, in_w, EE, ppart);
    epi_q<<<BB * TT, 128>>>(in_b);

    // attention: chunked flash partials, combine
    attn_chunk<<<dim3(HH, BB, NC), 256>>>();
    attn_combine<<<dim3(HH, BB), 256>>>();

    // out_proj split-K partials, then fused (sum + bias + residual + LN)
    gemm_splitk<<<dim3(EE / 64, (BB * TT) / 64, 4), 256>>>(
        po, EE, nullptr, out_w, EE, ppart);
    epi_ln<<<BB * TT, 128>>>(out_b, ln_g, ln_b);

    // FFN split-K partials, then fused (sum + bias + GELU + residual)
    gemm_splitk<<<dim3(EE / 64, (BB * TT) / 64, 4), 256>>>(
        pz, EE, nullptr, ffn_w, EE, ppart);
    epi_ffn<<<BB * TT, 128>>>(ffn_b, out);
}

// round 16
// speedup vs baseline: 1.6688x; 1.3312x over previous
#include <cuda_runtime.h>
#include <cuda_bf16.h>
#include <cstdint>
#include <math.h>

#define BB 16
#define NN 32768
#define DD 256
#define EE 512
#define HH 8
#define KK 512
#define TT 16
#define NC 4      // attention key chunks
#define CK 128    // keys per chunk

typedef __nv_bfloat16 bf16;

// ---------------- device scratch (no allocations allowed) ----------------
__device__ float g_x[BB * TT * EE];          // x for the 16 live rows/batch
__device__ bf16  g_wfh[2 * EE * DD];         // fused kv weight hi/lo [1024x256]
__device__ bf16  g_wfl[2 * EE * DD];
__device__ float g_wqp[EE * DD];             // fused q weight (x0.125) [512x256]
__device__ float g_bf[2 * EE];               // fused kv bias
__device__ float g_bq[EE];                   // fused q bias (x0.125)
__device__ float g_kv[BB * KK * 2 * EE];     // k|v concat fp32
__device__ float g_q[BB * TT * EE];          // scaled q
__device__ float g_o[BB * TT * EE];          // attn out
__device__ float g_z[BB * TT * EE];          // post layernorm
__device__ float g_part[4 * BB * TT * EE];   // split-K / attn partials
__device__ float g_m[NC * BB * HH * TT];
__device__ float g_l[NC * BB * HH * TT];
__device__ int   g_idx[BB * KK];

// order-preserving float->uint key (bigger key == bigger float)
__device__ __forceinline__ unsigned fkey(float f) {
    unsigned u = __float_as_uint(f);
    return (u & 0x80000000u) ? ~u : (u | 0x80000000u);
}

__device__ __forceinline__ void split_bf16(float f, bf16& h, bf16& l) {
    h = __float2bfloat16(f);
    l = __float2bfloat16(f - __bfloat162float(h));
}

__device__ __forceinline__ uint32_t pk2(bf16 a, bf16 b) {
    return (uint32_t)__bfloat16_as_ushort(a) |
           ((uint32_t)__bfloat16_as_ushort(b) << 16);
}

// split 8 floats (two float4) into packed hi uint4 / lo uint4
__device__ __forceinline__ void pack8(float4 a, float4 b, uint4& h, uint4& l) {
    bf16 h0, l0, h1, l1;
    split_bf16(a.x, h0, l0); split_bf16(a.y, h1, l1);
    h.x = pk2(h0, h1); l.x = pk2(l0, l1);
    split_bf16(a.z, h0, l0); split_bf16(a.w, h1, l1);
    h.y = pk2(h0, h1); l.y = pk2(l0, l1);
    split_bf16(b.x, h0, l0); split_bf16(b.y, h1, l1);
    h.z = pk2(h0, h1); l.z = pk2(l0, l1);
    split_bf16(b.z, h0, l0); split_bf16(b.w, h1, l1);
    h.w = pk2(h0, h1); l.w = pk2(l0, l1);
}

__device__ __forceinline__ void cp16(uint32_t s, const void* g) {
    asm volatile("cp.async.cg.shared.global [%0], [%1], 16;" :: "r"(s), "l"(g));
}

// ---------------- top-K: smem-resident keys, radix select + bitonic sort ----
extern __shared__ unsigned skeys[];   // NN unsigned = 128 KB dynamic smem

__global__ void __launch_bounds__(1024) topk_kernel(const float* __restrict__ scores) {
    const int b = blockIdx.x;
    const float* s = scores + (size_t)b * NN;
    const int tid = threadIdx.x;

    __shared__ unsigned hist[256];
    __shared__ unsigned sh_prefix, sh_mask, sh_remk;
    __shared__ int sh_cntgt, sh_cnteq;
    __shared__ unsigned long long sel[512];
    __shared__ int eq[1024];

    if (tid == 0) { sh_prefix = 0u; sh_mask = 0u; sh_remk = KK; }
    if (tid < 256) hist[tid] = 0u;
    __syncthreads();

    for (int i = tid; i < NN; i += 1024) {
        unsigned k = fkey(__ldg(&s[i]));
        skeys[i] = k;
        atomicAdd(&hist[k >> 24], 1u);
    }
    __syncthreads();

    for (int pass = 0; pass < 4; pass++) {
        const int shift = 24 - pass * 8;
        if (tid == 0) {
            unsigned remk = sh_remk, acc = 0u;
            int d;
            for (d = 255; d >= 0; d--) {
                if (acc + hist[d] >= remk) break;
                acc += hist[d];
            }
            sh_remk  = remk - acc;
            sh_prefix = sh_prefix | ((unsigned)d << shift);
            sh_mask   = sh_mask | (0xFFu << shift);
            sh_cntgt = 0; sh_cnteq = 0;
        }
        __syncthreads();
        if (pass == 3) break;
        if (tid < 256) hist[tid] = 0u;
        __syncthreads();
        const unsigned prefix = sh_prefix, mask = sh_mask;
        const int nshift = shift - 8;
        for (int i = tid; i < NN; i += 1024) {
            unsigned k = skeys[i];
            if ((k & mask) == prefix) atomicAdd(&hist[(k >> nshift) & 255u], 1u);
        }
        __syncthreads();
    }

    const unsigned Tkey = sh_prefix;
    const int remk = (int)sh_remk;

    for (int i = tid; i < NN; i += 1024) {
        unsigned k = skeys[i];
        if (k > Tkey) {
            int p = atomicAdd(&sh_cntgt, 1);
            sel[p] = ((unsigned long long)k << 32) | (unsigned)(0xFFFFFFFFu - (unsigned)i);
        } else if (k == Tkey) {
            int p = atomicAdd(&sh_cnteq, 1);
            if (p < 1024) eq[p] = i;
        }
    }
    __syncthreads();
    const int cntgt = sh_cntgt;
    const int cnteq = min(sh_cnteq, 1024);

    if (tid >= cnteq) eq[tid] = 0x7FFFFFFF;
    __syncthreads();
    for (unsigned k = 2; k <= 1024; k <<= 1)
        for (unsigned j = k >> 1; j > 0; j >>= 1) {
            unsigned i = tid, ixj = i ^ j;
            if (ixj > i) {
                int a = eq[i], c = eq[ixj];
                bool up = ((i & k) == 0);
                if ((a > c) == up) { eq[i] = c; eq[ixj] = a; }
            }
            __syncthreads();
        }
    for (int jj = tid; jj < remk; jj += 1024)
        sel[cntgt + jj] = ((unsigned long long)Tkey << 32) |
                          (unsigned)(0xFFFFFFFFu - (unsigned)eq[jj]);
    __syncthreads();

    for (unsigned k = 2; k <= 512; k <<= 1)
        for (unsigned j = k >> 1; j > 0; j >>= 1) {
            if (tid < 512) {
                unsigned i = tid, ixj = i ^ j;
                if (ixj > i) {
                    unsigned long long a = sel[i], c = sel[ixj];
                    bool up = ((i & k) == 0);
                    if ((a > c) == up) { sel[i] = c; sel[ixj] = a; }
                }
            }
            __syncthreads();
        }
    if (tid < 512)
        g_idx[b * KK + tid] =
            (int)(0xFFFFFFFFu - (unsigned)(sel[511 - tid] & 0xFFFFFFFFull));
}

// -------- wfuse_all: fused weights + biases for kv AND q -------------------
// rt 0..15 : kv rows (in_w rows 512..1535) -> g_wfh/g_wfl (bf16 h/l)
// rt 16..23: q  rows (in_w rows 0..511)    -> g_wqp (fp32, x0.125)
// blockIdx.x==0 blocks also compute the fused biases for their rows.
__global__ void __launch_bounds__(256)
wfuse_all(const float* __restrict__ in_w, const float* __restrict__ Wp,
          const float* __restrict__ pb, const float* __restrict__ in_b) {
    const int rt = blockIdx.y;                     // 0..23
    const bool iskv = (rt < 16);
    const int aRow0 = iskv ? (EE + rt * 64) : ((rt - 16) * 64);
    const int oRow0 = iskv ? (rt * 64) : ((rt - 16) * 64);
    const int col0 = blockIdx.x * 64;
    const int tid = threadIdx.x;
    const int tx4 = (tid & 15) * 4, ty4 = (tid >> 4) * 4;
    __shared__ float As[16][68];
    __shared__ float Bs[16][68];
    const int ar = tid >> 2, ac = (tid & 3) << 2;    // A loader
    const int br = tid >> 4, bc = (tid & 15) << 2;   // B loader

    float acc[4][4];
#pragma unroll
    for (int i = 0; i < 4; i++)
#pragma unroll
        for (int j = 0; j < 4; j++) acc[i][j] = 0.f;

    for (int k0 = 0; k0 < EE; k0 += 16) {
        float4 av = *(const float4*)(in_w + (size_t)(aRow0 + ar) * EE + k0 + ac);
        float4 bv = *(const float4*)(Wp + (size_t)(k0 + br) * DD + col0 + bc);
        __syncthreads();
        As[ac + 0][ar] = av.x; As[ac + 1][ar] = av.y;
        As[ac + 2][ar] = av.z; As[ac + 3][ar] = av.w;
        *(float4*)&Bs[br][bc] = bv;
        __syncthreads();
#pragma unroll
        for (int k = 0; k < 16; k++) {
            float a[4], bb[4];
            *(float4*)a  = *(const float4*)&As[k][ty4];
            *(float4*)bb = *(const float4*)&Bs[k][tx4];
#pragma unroll
            for (int i = 0; i < 4; i++)
#pragma unroll
                for (int j = 0; j < 4; j++)
                    acc[i][j] = fmaf(a[i], bb[j], acc[i][j]);
        }
    }
#pragma unroll
    for (int i = 0; i < 4; i++)
#pragma unroll
        for (int j = 0; j < 4; j++) {
            int r = oRow0 + ty4 + i, c = col0 + tx4 + j;
            if (iskv) {
                bf16 h, l;
                split_bf16(acc[i][j], h, l);
                g_wfh[(size_t)r * DD + c] = h;
                g_wfl[(size_t)r * DD + c] = l;
            } else {
                g_wqp[(size_t)r * DD + c] = acc[i][j] * 0.125f;
            }
        }

    // fused biases (one column-block per row-tile does them)
    if (blockIdx.x == 0) {
        const int warp = tid >> 5, lane = tid & 31;   // 8 warps x 8 rows
        for (int rr = warp; rr < 64; rr += 8) {
            const float* wrow = in_w + (size_t)(aRow0 + rr) * EE;
            float s = 0.f;
            for (int e = lane; e < EE; e += 32) s = fmaf(wrow[e], pb[e], s);
#pragma unroll
            for (int o = 16; o > 0; o >>= 1)
                s += __shfl_xor_sync(0xFFFFFFFFu, s, o);
            if (lane == 0) {
                if (iskv) g_bf[oRow0 + rr] = s + in_b[EE + oRow0 + rr];
                else      g_bq[oRow0 + rr] = (s + in_b[oRow0 + rr]) * 0.125f;
            }
        }
    }
}

// ============== tensor-core split-bf16 GEMM (kv from gathered feats) =======
#define AP 40
#define SA_ELEM (128 * AP)
#define SW_ELEM (128 * AP)
#define TC_SMEM ((2 * SA_ELEM + 2 * SW_ELEM) * 2 * 2)  // 81920 bytes

__device__ __forceinline__ void ldsm4(uint32_t r[4], uint32_t addr) {
    asm volatile("ldmatrix.sync.aligned.m8n8.x4.shared.b16 {%0,%1,%2,%3}, [%4];"
                 : "=r"(r[0]), "=r"(r[1]), "=r"(r[2]), "=r"(r[3]) : "r"(addr));
}
__device__ __forceinline__ void mma_bf16(float c[4], const uint32_t a[4],
                                         uint32_t b0, uint32_t b1) {
    asm volatile(
        "mma.sync.aligned.m16n8k16.row.col.f32.bf16.bf16.f32 "
        "{%0,%1,%2,%3}, {%4,%5,%6,%7}, {%8,%9}, {%0,%1,%2,%3};"
        : "+f"(c[0]), "+f"(c[1]), "+f"(c[2]), "+f"(c[3])
        : "r"(a[0]), "r"(a[1]), "r"(a[2]), "r"(a[3]), "r"(b0), "r"(b1));
}

#define LOAD_A_F32(K0)                                                    \
    {                                                                     \
        float4 x0 = *(const float4*)(gA0 + (K0));                         \
        float4 x1 = *(const float4*)(gA0 + (K0) + 4);                     \
        float4 y0 = *(const float4*)(gA1 + (K0));                         \
        float4 y1 = *(const float4*)(gA1 + (K0) + 4);                     \
        pack8(x0, x1, pAh0, pAl0);                                        \
        pack8(y0, y1, pAh1, pAl1);                                        \
    }

#define LOAD_W_ASYNC(BUF, K0)                                             \
    {                                                                     \
        cp16(baseWh + 2u * ((BUF) * SW_ELEM + arow * AP + achk), gWh0 + (K0)); \
        cp16(baseWh + 2u * ((BUF) * SW_ELEM + (arow + 64) * AP + achk), gWh1 + (K0)); \
        cp16(baseWl + 2u * ((BUF) * SW_ELEM + arow * AP + achk), gWl0 + (K0)); \
        cp16(baseWl + 2u * ((BUF) * SW_ELEM + (arow + 64) * AP + achk), gWl1 + (K0)); \
    }

#define CP_COMMIT() asm volatile("cp.async.commit_group;\n" ::: "memory")
#define CP_WAIT0()  asm volatile("cp.async.wait_group 0;\n" ::: "memory")

#define STS_A(BUF)                                                        \
    {                                                                     \
        *(uint4*)&sAh[(BUF) * SA_ELEM + arow * AP + achk]        = pAh0;  \
        *(uint4*)&sAh[(BUF) * SA_ELEM + (arow + 64) * AP + achk] = pAh1;  \
        *(uint4*)&sAl[(BUF) * SA_ELEM + arow * AP + achk]        = pAl0;  \
        *(uint4*)&sAl[(BUF) * SA_ELEM + (arow + 64) * AP + achk] = pAl1;  \
    }

#define TC_COMPUTE(BUF)                                                   \
    _Pragma("unroll")                                                     \
    for (int ks = 0; ks < 32; ks += 16) {                                 \
        uint32_t ah[2][4], al[2][4];                                      \
        _Pragma("unroll")                                                 \
        for (int mt = 0; mt < 2; mt++) {                                  \
            uint32_t off = 2u * ((BUF) * SA_ELEM + (wm + mt * 16) * AP + aoffA + ks); \
            ldsm4(ah[mt], baseAh + off);                                  \
            ldsm4(al[mt], baseAl + off);                                  \
        }                                                                 \
        _Pragma("unroll")                                                 \
        for (int hf = 0; hf < 2; hf++) {                                  \
            uint32_t wh[2][4], wl[2][4];                                  \
            _Pragma("unroll")                                             \
            for (int np = 0; np < 2; np++) {                              \
                uint32_t off = 2u * ((BUF) * SW_ELEM + (wn + (hf * 2 + np) * 16) * AP + woffW + ks); \
                ldsm4(wh[np], baseWh + off);                              \
                ldsm4(wl[np], baseWl + off);                              \
            }                                                             \
            _Pragma("unroll")                                             \
            for (int mt = 0; mt < 2; mt++)                                \
                _Pragma("unroll")                                         \
                for (int nt = 0; nt < 4; nt++) {                          \
                    uint32_t bh0 = wh[nt >> 1][(nt & 1) * 2];             \
                    uint32_t bh1 = wh[nt >> 1][(nt & 1) * 2 + 1];         \
                    uint32_t bl0 = wl[nt >> 1][(nt & 1) * 2];             \
                    uint32_t bl1 = wl[nt >> 1][(nt & 1) * 2 + 1];         \
                    mma_bf16(acc[mt][hf * 4 + nt], ah[mt], bh0, bh1);     \
                    mma_bf16(acc[mt][hf * 4 + nt], ah[mt], bl0, bl1);     \
                    mma_bf16(acc[mt][hf * 4 + nt], al[mt], bh0, bh1);     \
                }                                                         \
        }                                                                 \
    }

// kv = feats[idx] @ Wfuse^T + bias_fuse   (Kd = 256, N = 1024)
__global__ void __launch_bounds__(256, 2)
gemm_tc_kv(const bf16* __restrict__ Wh, const bf16* __restrict__ Wl,
           const float* __restrict__ bias,
           float* __restrict__ C, long long strideC,
           int Kd,
           const int* __restrict__ idxp, const float* __restrict__ gfeat) {
    extern __shared__ __align__(16) char smraw[];
    bf16* sAh = (bf16*)smraw;
    bf16* sAl = sAh + 2 * SA_ELEM;
    bf16* sWh = sAl + 2 * SA_ELEM;
    bf16* sWl = sWh + 2 * SW_ELEM;
    const int b = blockIdx.z;
    const int row0 = blockIdx.y * 128, col0 = blockIdx.x * 128;
    const int N = gridDim.x * 128;
    const int tid = threadIdx.x;
    const int lane = tid & 31, wid = tid >> 5;
    const int wm = (wid & 3) * 32, wn = (wid >> 2) * 64;
    const uint32_t baseAh = (uint32_t)__cvta_generic_to_shared(sAh);
    const uint32_t baseAl = (uint32_t)__cvta_generic_to_shared(sAl);
    const uint32_t baseWh = (uint32_t)__cvta_generic_to_shared(sWh);
    const uint32_t baseWl = (uint32_t)__cvta_generic_to_shared(sWl);
    const uint32_t aoffA = (lane & 15) * AP + ((lane >> 4) << 3);
    const uint32_t woffW = ((lane & 7) + ((lane & 16) >> 1)) * AP + (lane & 8);
    const int arow = tid >> 2;
    const int achk = (tid & 3) * 8;

    const int* ib = idxp + b * KK;
    const float* gA0 = gfeat + ((size_t)b * NN + ib[row0 + arow]) * Kd + achk;
    const float* gA1 = gfeat + ((size_t)b * NN + ib[row0 + arow + 64]) * Kd + achk;
    const bf16* gWh0 = Wh + (size_t)(col0 + arow) * Kd + achk;
    const bf16* gWh1 = Wh + (size_t)(col0 + arow + 64) * Kd + achk;
    const bf16* gWl0 = Wl + (size_t)(col0 + arow) * Kd + achk;
    const bf16* gWl1 = Wl + (size_t)(col0 + arow + 64) * Kd + achk;

    float acc[2][8][4];
#pragma unroll
    for (int mt = 0; mt < 2; mt++)
#pragma unroll
        for (int nt = 0; nt < 8; nt++)
#pragma unroll
            for (int i = 0; i < 4; i++) acc[mt][nt][i] = 0.f;

    uint4 pAh0, pAh1, pAl0, pAl1;
    LOAD_A_F32(0)
    LOAD_W_ASYNC(0, 0)
    CP_COMMIT();
    STS_A(0)
    CP_WAIT0();
    __syncthreads();

    int buf = 0;
    for (int k0 = 32; k0 < Kd; k0 += 32) {
        LOAD_A_F32(k0)
        LOAD_W_ASYNC(buf ^ 1, k0)
        CP_COMMIT();
        TC_COMPUTE(buf)
        STS_A(buf ^ 1)
        CP_WAIT0();
        __syncthreads();
        buf ^= 1;
    }
    TC_COMPUTE(buf)

    const int g = lane >> 2, tq = (lane & 3) * 2;
#pragma unroll
    for (int mt = 0; mt < 2; mt++)
#pragma unroll
        for (int nt = 0; nt < 8; nt++) {
            int r = row0 + wm + mt * 16 + g;
            int cc = col0 + wn + nt * 8 + tq;
            float b0 = bias[cc], b1 = bias[cc + 1];
            size_t i0 = (size_t)((long long)b * strideC) + (size_t)r * N + cc;
            size_t i1 = (size_t)((long long)b * strideC) + (size_t)(r + 8) * N + cc;
            *(float2*)(C + i0) = make_float2(acc[mt][nt][0] + b0, acc[mt][nt][1] + b1);
            *(float2*)(C + i1) = make_float2(acc[mt][nt][2] + b0, acc[mt][nt][3] + b1);
        }
}

// ============ split-K GEMM partials (dual weight source for xq) ============
// idxp != null: A row m -> gfeat row (b*NN + idx[b*KK + (m&15)]), b = m>>4.
// Wb != null: columns >= 512 come from Wb (rows col-512), else Wa.
#define SKP 68

#define SK_STS(BUF)                                                       \
    {                                                                     \
        float* as = As[BUF]; float* bs = Bs[BUF];                         \
        as[(lc + 0) * SKP + lr] = av.x;                                   \
        as[(lc + 1) * SKP + lr] = av.y;                                   \
        as[(lc + 2) * SKP + lr] = av.z;                                   \
        as[(lc + 3) * SKP + lr] = av.w;                                   \
        bs[(lc + 0) * SKP + lr] = bv.x;                                   \
        bs[(lc + 1) * SKP + lr] = bv.y;                                   \
        bs[(lc + 2) * SKP + lr] = bv.z;                                   \
        bs[(lc + 3) * SKP + lr] = bv.w;                                   \
    }

#define SK_COMPUTE(BUF)                                                   \
    _Pragma("unroll")                                                     \
    for (int k = 0; k < 16; k++) {                                        \
        float a[4], bb[4];                                                \
        *(float4*)a  = *(const float4*)&As[BUF][k * SKP + ty4];           \
        *(float4*)bb = *(const float4*)&Bs[BUF][k * SKP + tx4];           \
        _Pragma("unroll")                                                 \
        for (int i = 0; i < 4; i++)                                       \
            _Pragma("unroll")                                             \
            for (int j = 0; j < 4; j++)                                   \
                acc[i][j] = fmaf(a[i], bb[j], acc[i][j]);                 \
    }

__global__ void __launch_bounds__(256)
gemm_splitk(const float* __restrict__ A, int astride,
            const int* __restrict__ idxp,
            const float* __restrict__ Wa, const float* __restrict__ Wb,
            int wstride,
            float* __restrict__ part, int nTot) {
    const int kc = blockIdx.z;
    const int row0 = blockIdx.y * 64, col0 = blockIdx.x * 64;
    const int tid = threadIdx.x;
    const int tx4 = (tid & 15) * 4, ty4 = (tid >> 4) * 4;
    const int lr = tid >> 2, lc = (tid & 3) << 2;

    __shared__ __align__(16) float As[2][16 * SKP];
    __shared__ __align__(16) float Bs[2][16 * SKP];

    const int m = row0 + lr;
    size_t arow;
    if (idxp) {
        int bb = m >> 4;
        arow = (size_t)bb * NN + idxp[bb * KK + (m & 15)];
    } else {
        arow = (size_t)m;
    }
    const float* Ar = A + arow * astride + kc * 128 + lc;
    const float* Wsrc;
    int wrow;
    if (Wb && col0 >= 512) { Wsrc = Wb; wrow = col0 - 512 + lr; }
    else                   { Wsrc = Wa; wrow = col0 + lr; }
    const float* Wr = Wsrc + (size_t)wrow * wstride + kc * 128 + lc;

    float acc[4][4];
#pragma unroll
    for (int i = 0; i < 4; i++)
#pragma unroll
        for (int j = 0; j < 4; j++) acc[i][j] = 0.f;

    float4 av = *(const float4*)(Ar);
    float4 bv = *(const float4*)(Wr);
    SK_STS(0)
    __syncthreads();

    int buf = 0;
#pragma unroll
    for (int k0 = 16; k0 < 128; k0 += 16) {
        av = *(const float4*)(Ar + k0);
        bv = *(const float4*)(Wr + k0);
        SK_COMPUTE(buf)
        SK_STS(buf ^ 1)
        __syncthreads();
        buf ^= 1;
    }
    SK_COMPUTE(buf)

    float* pp = part + (size_t)kc * (size_t)(BB * TT) * nTot;
#pragma unroll
    for (int i = 0; i < 4; i++) {
        float4 v;
        v.x = acc[i][0]; v.y = acc[i][1]; v.z = acc[i][2]; v.w = acc[i][3];
        *(float4*)(pp + (size_t)(row0 + ty4 + i) * nTot + col0 + tx4) = v;
    }
}

// -------- epi_xq: cols 0-511 -> g_x (+pb); cols 512-1023 -> g_q (+g_bq) ----
__global__ void __launch_bounds__(128)
epi_xq(const float* __restrict__ pb) {
    const int row = blockIdx.x;
    const int tid = threadIdx.x;
#pragma unroll
    for (int u = 0; u < 8; u++) {
        int e = tid + u * 128;
        size_t o = (size_t)row * 1024 + e;
        float v = g_part[o] + g_part[(size_t)(BB * TT) * 1024 + o];
        if (e < EE) g_x[(size_t)row * EE + e] = v + pb[e];
        else        g_q[(size_t)row * EE + (e - EE)] = v + g_bq[e - EE];
    }
}

// -------- attention chunk: partial softmax numerator over 128 keys ---------
__global__ void __launch_bounds__(256)
attn_chunk() {
    const int h = blockIdx.x, b = blockIdx.y, c = blockIdx.z;
    const float* kb = g_kv + (size_t)b * KK * 2 * EE + h * 64;
    const float* vb = kb + EE;

    __shared__ float qs[TT][64];
    __shared__ float ks[CK * 65];
    __shared__ float lg[TT][CK];
    __shared__ float vs[32][68];
    const int tid = threadIdx.x;

    {
        int t = tid >> 4;
        int d = (tid * 4) & 63;
        *(float4*)&qs[t][d] =
            *(const float4*)(g_q + ((size_t)b * TT + t) * EE + h * 64 + d);
    }
    const int vr = tid >> 4, vc = (tid & 15) * 4;
    for (int r0 = 0; r0 < CK; r0 += 16) {
        float4 k4 = *(const float4*)(kb + (size_t)(c * CK + r0 + vr) * (2 * EE) + vc);
        float* kp = &ks[(r0 + vr) * 65 + vc];
        kp[0] = k4.x; kp[1] = k4.y; kp[2] = k4.z; kp[3] = k4.w;
    }
    __syncthreads();

    {
        const int kk = tid & 127, th = tid >> 7;
        float acc[8];
#pragma unroll
        for (int i = 0; i < 8; i++) acc[i] = 0.f;
        const float* kr = &ks[kk * 65];
#pragma unroll 8
        for (int d = 0; d < 64; d++) {
            float kv = kr[d];
#pragma unroll
            for (int i = 0; i < 8; i++)
                acc[i] = fmaf(qs[th * 8 + i][d], kv, acc[i]);
        }
#pragma unroll
        for (int i = 0; i < 8; i++) lg[th * 8 + i][kk] = acc[i];
    }
    __syncthreads();

    const int w = tid >> 5, lane = tid & 31;
    for (int t = w; t < TT; t += 8) {
        float m = -1e30f;
        for (int i = lane; i < CK; i += 32) m = fmaxf(m, lg[t][i]);
#pragma unroll
        for (int o = 16; o > 0; o >>= 1) m = fmaxf(m, __shfl_xor_sync(0xFFFFFFFFu, m, o));
        float ssum = 0.f;
        for (int i = lane; i < CK; i += 32) {
            float e = __expf(lg[t][i] - m);
            lg[t][i] = e; ssum += e;
        }
#pragma unroll
        for (int o = 16; o > 0; o >>= 1) ssum += __shfl_xor_sync(0xFFFFFFFFu, ssum, o);
        if (lane == 0) {
            g_m[((size_t)(c * BB + b) * HH + h) * TT + t] = m;
            g_l[((size_t)(c * BB + b) * HH + h) * TT + t] = ssum;
        }
    }

    const int d = tid & 63, tg = tid >> 6;
    float acc4[4] = {0.f, 0.f, 0.f, 0.f};
    for (int kk0 = 0; kk0 < CK; kk0 += 32) {
        __syncthreads();
        const float* vrow = vb + (size_t)(c * CK + kk0 + vr) * (2 * EE) + vc;
        float4 v0 = *(const float4*)(vrow);
        float4 v1 = *(const float4*)(vrow + (size_t)16 * 2 * EE);
        *(float4*)&vs[vr][vc]      = v0;
        *(float4*)&vs[vr + 16][vc] = v1;
        __syncthreads();
#pragma unroll
        for (int r = 0; r < 32; r++) {
            float v = vs[r][d];
#pragma unroll
            for (int i = 0; i < 4; i++)
                acc4[i] = fmaf(lg[tg + i * 4][kk0 + r], v, acc4[i]);
        }
    }
#pragma unroll
    for (int i = 0; i < 4; i++)
        g_part[((size_t)(c * BB + b) * TT + tg + i * 4) * EE + h * 64 + d] = acc4[i];
}

// -------- attention combine: merge 4 chunks -> g_o ------------------------
__global__ void __launch_bounds__(256)
attn_combine() {
    const int h = blockIdx.x, b = blockIdx.y;
    const int tid = threadIdx.x;
    const int d = tid & 63, tg = tid >> 6;
#pragma unroll
    for (int i = 0; i < 4; i++) {
        const int t = tg + i * 4;
        float m[NC], l[NC];
#pragma unroll
        for (int c = 0; c < NC; c++) {
            m[c] = g_m[((size_t)(c * BB + b) * HH + h) * TT + t];
            l[c] = g_l[((size_t)(c * BB + b) * HH + h) * TT + t];
        }
        float mstar = fmaxf(fmaxf(m[0], m[1]), fmaxf(m[2], m[3]));
        float wgt[NC], denom = 0.f;
#pragma unroll
        for (int c = 0; c < NC; c++) {
            wgt[c] = __expf(m[c] - mstar);
            denom += wgt[c] * l[c];
        }
        float o = 0.f;
#pragma unroll
        for (int c = 0; c < NC; c++)
            o += wgt[c] *
                 g_part[((size_t)(c * BB + b) * TT + t) * EE + h * 64 + d];
        g_o[((size_t)b * TT + t) * EE + h * 64 + d] = o / denom;
    }
}

// -------- epilogue 1: y = sum(part) + bo + x_res ; z = LN(y) --------------
__global__ void __launch_bounds__(128)
epi_ln(const float* __restrict__ bo,
       const float* __restrict__ lng, const float* __restrict__ lnb) {
    const int row = blockIdx.x;
    const int tid = threadIdx.x;
    const float* xres = g_x + (size_t)row * EE;
    float* zr = g_z + (size_t)row * EE;
    __shared__ float red[4];

    float v[4];
#pragma unroll
    for (int u = 0; u < 4; u++) {
        int e = tid + u * 128;
        size_t o = (size_t)row * EE + e;
        float s = g_part[o] + g_part[o + 1 * BB * TT * EE] +
                  g_part[o + 2 * BB * TT * EE] + g_part[o + 3 * BB * TT * EE];
        v[u] = s + bo[e] + xres[e];
    }

    float s = v[0] + v[1] + v[2] + v[3];
#pragma unroll
    for (int o = 16; o > 0; o >>= 1) s += __shfl_xor_sync(0xFFFFFFFFu, s, o);
    if ((tid & 31) == 0) red[tid >> 5] = s;
    __syncthreads();
    const float mu = (red[0] + red[1] + red[2] + red[3]) / EE;
    __syncthreads();

    float q = 0.f;
#pragma unroll
    for (int u = 0; u < 4; u++) { float dlt = v[u] - mu; q += dlt * dlt; }
#pragma unroll
    for (int o = 16; o > 0; o >>= 1) q += __shfl_xor_sync(0xFFFFFFFFu, q, o);
    if ((tid & 31) == 0) red[tid >> 5] = q;
    __syncthreads();
    const float rstd = rsqrtf((red[0] + red[1] + red[2] + red[3]) / EE + 1e-5f);

#pragma unroll
    for (int u = 0; u < 4; u++) {
        int e = tid + u * 128;
        zr[e] = (v[u] - mu) * rstd * lng[e] + lnb[e];
    }
}

// -------- epilogue 2: out = z + gelu(sum(part) + bf) ----------------------
__global__ void __launch_bounds__(128)
epi_ffn(const float* __restrict__ bf, float* __restrict__ out) {
    const int row = blockIdx.x;
    const int tid = threadIdx.x;
    const float* zr = g_z + (size_t)row * EE;
    float* outp = out + (size_t)row * EE;
#pragma unroll
    for (int u = 0; u < 4; u++) {
        int e = tid + u * 128;
        size_t o = (size_t)row * EE + e;
        float t = g_part[o] + g_part[o + 1 * BB * TT * EE] +
                  g_part[o + 2 * BB * TT * EE] + g_part[o + 3 * BB * TT * EE] +
                  bf[e];
        float g = 0.5f * t * (1.f + erff(t * 0.70710678118654752f));
        outp[e] = zr[e] + g;
    }
}

// ---------------- launch ----------------
extern "C" void kernel_launch(void* const* d_in, const int* in_sizes, int n_in,
                              void* d_out, int out_size) {
    (void)in_sizes; (void)n_in; (void)out_size;
    const float* feats  = (const float*)d_in[0];
    const float* scores = (const float*)d_in[1];
    const float* proj_w = (const float*)d_in[2];
    const float* proj_b = (const float*)d_in[3];
    const float* in_w   = (const float*)d_in[4];
    const float* in_b   = (const float*)d_in[5];
    const float* out_w  = (const float*)d_in[6];
    const float* out_b  = (const float*)d_in[7];
    const float* ln_g   = (const float*)d_in[8];
    const float* ln_b   = (const float*)d_in[9];
    const float* ffn_w  = (const float*)d_in[10];
    const float* ffn_b  = (const float*)d_in[11];
    float* out = (float*)d_out;

    float *px, *pkv, *po, *pz, *ppart, *pbf, *pwqp;
    bf16 *pwfh, *pwfl;
    int* pidx;
    cudaGetSymbolAddress((void**)&px,    g_x);
    cudaGetSymbolAddress((void**)&pkv,   g_kv);
    cudaGetSymbolAddress((void**)&po,    g_o);
    cudaGetSymbolAddress((void**)&pz,    g_z);
    cudaGetSymbolAddress((void**)&ppart, g_part);
    cudaGetSymbolAddress((void**)&pidx,  g_idx);
    cudaGetSymbolAddress((void**)&pwfh,  g_wfh);
    cudaGetSymbolAddress((void**)&pwfl,  g_wfl);
    cudaGetSymbolAddress((void**)&pwqp,  g_wqp);
    cudaGetSymbolAddress((void**)&pbf,   g_bf);

    static int inited = 0;
    static cudaStream_t s2;
    static cudaEvent_t evRoot, evWF, evTK, evXQ;
    if (!inited) {
        cudaFuncSetAttribute(topk_kernel,
                             cudaFuncAttributeMaxDynamicSharedMemorySize,
                             NN * (int)sizeof(unsigned));
        cudaFuncSetAttribute(gemm_tc_kv,
                             cudaFuncAttributeMaxDynamicSharedMemorySize,
                             TC_SMEM);
        cudaStreamCreateWithFlags(&s2, cudaStreamNonBlocking);
        cudaEventCreateWithFlags(&evRoot, cudaEventDisableTiming);
        cudaEventCreateWithFlags(&evWF,   cudaEventDisableTiming);
        cudaEventCreateWithFlags(&evTK,   cudaEventDisableTiming);
        cudaEventCreateWithFlags(&evXQ,   cudaEventDisableTiming);
        inited = 1;
    }

    // fork side stream from the main (captured) stream
    cudaEventRecord(evRoot, 0);
    cudaStreamWaitEvent(s2, evRoot, 0);

    // s2: fused weights + biases (kv bf16 h/l, q fp32 pre-scaled)
    wfuse_all<<<dim3(DD / 64, 24), 256, 0, s2>>>(in_w, proj_w, proj_b, in_b);
    cudaEventRecord(evWF, s2);

    // main: top-k (runs concurrently with wfuse_all)
    topk_kernel<<<BB, 1024, NN * sizeof(unsigned)>>>(scores);
    cudaEventRecord(evTK, 0);

    // s2: xq = feats16 @ [Wp | Wqp]^T  (needs topk)  -> g_x, g_q
    cudaStreamWaitEvent(s2, evTK, 0);
    gemm_splitk<<<dim3(16, 4, 2), 256, 0, s2>>>(
        feats, DD, pidx, proj_w, pwqp, DD, ppart, 1024);
    epi_xq<<<BB * TT, 128, 0, s2>>>(proj_b);
    cudaEventRecord(evXQ, s2);

    // main: kv = feats[idx] @ Wfuse^T + bias_fuse  (needs wfuse + topk)
    cudaStreamWaitEvent(0, evWF, 0);
    gemm_tc_kv<<<dim3(2 * EE / 128, KK / 128, BB), 256, TC_SMEM>>>(
        pwfh, pwfl, pbf, pkv, (long long)KK * 2 * EE, DD, pidx, feats);

    // join: attention needs q (s2) + kv (main)
    cudaStreamWaitEvent(0, evXQ, 0);
    attn_chunk<<<dim3(HH, BB, NC), 256>>>();
    attn_combine<<<dim3(HH, BB), 256>>>();

    // out_proj split-K, fused (sum + bias + residual + LN)
    gemm_splitk<<<dim3(EE / 64, (BB * TT) / 64, 4), 256>>>(
        po, EE, nullptr, out_w, nullptr, EE, ppart, EE);
    epi_ln<<<BB * TT, 128>>>(out_b, ln_g, ln_b);

    // FFN split-K, fused (sum + bias + GELU + residual)
    gemm_splitk<<<dim3(EE / 64, (BB * TT) / 64, 4), 256>>>(
        pz, EE, nullptr, ffn_w, nullptr, EE, ppart, EE);
    epi_ffn<<<BB * TT, 128>>>(ffn_b, out);
}